// round 12
// baseline (speedup 1.0000x reference)
#include <cuda_runtime.h>

#define BB 2
#define NN 16384
#define KK 16
#define CC 64
#define AA 8
#define PTS (BB*NN)          // 32768 points
#define ITEMS (PTS*KK)       // 524288 (b,n,k) items
#define EVEN_GRID 592        // 4 blocks * 148 SMs

// ---------------- scratch (device globals; no allocation allowed) ----------
__device__ float    g_q [PTS*CC];
__device__ float    g_k [PTS*CC];
__device__ float    g_v [PTS*CC];
__device__ float    g_d1[ITEMS*3];
__device__ float    g_x [ITEMS*CC];   // materialized attn_in (134 MB)
__device__ float    g_h1[ITEMS*AA];
// acc layout: [0..2]=d_sum [3..5]=d_sq [6..69]=g1_sum [70..133]=g1_sq
//             [134..141]=g2_sum [142..149]=g2_sq
__device__ double   g_acc[150];
// bn layout: [0..2]=a_d [3..5]=b_d [6..69]=a1 [70..133]=b1 [134..141]=a2 [142..149]=b2
__device__ float    g_bn[150];
__device__ unsigned g_ctr[4];    // 0=d1, 1=g1s, 2=h1

// 32-lane reduce of 8 partials -> full sum of part[a] on lanes where
// a = (lane>>2)&7.  9 shuffles total (value-splitting butterfly).
__device__ __forceinline__ float reduce8_split(const float part[8], int lane) {
    const bool h16 = (lane & 16);
    float np4[4];
    #pragma unroll
    for (int i = 0; i < 4; i++) {
        const float keep = h16 ? part[i+4] : part[i];
        const float give = h16 ? part[i]   : part[i+4];
        np4[i] = keep + __shfl_xor_sync(0xFFFFFFFFu, give, 16);
    }
    const bool h8 = (lane & 8);
    float np2[2];
    #pragma unroll
    for (int i = 0; i < 2; i++) {
        const float keep = h8 ? np4[i+2] : np4[i];
        const float give = h8 ? np4[i]   : np4[i+2];
        np2[i] = keep + __shfl_xor_sync(0xFFFFFFFFu, give, 8);
    }
    const bool h4 = (lane & 4);
    float v;
    {
        const float keep = h4 ? np2[1] : np2[0];
        const float give = h4 ? np2[0] : np2[1];
        v = keep + __shfl_xor_sync(0xFFFFFFFFu, give, 4);
    }
    v += __shfl_xor_sync(0xFFFFFFFFu, v, 1);
    v += __shfl_xor_sync(0xFFFFFFFFu, v, 2);
    return v;
}

// last-block detector: returns true in exactly one block, after all others
// have finished their g_acc contributions.
__device__ __forceinline__ bool last_block(int ctrId, int t, int* sFlag) {
    __syncthreads();
    if (t == 0) {
        __threadfence();
        *sFlag = (atomicAdd(&g_ctr[ctrId], 1u) == gridDim.x - 1) ? 1 : 0;
    }
    __syncthreads();
    return *sFlag != 0;
}

// ---------------- kernel 1: q/k/v linear (4x4 register-tiled GEMM) ---------
__global__ void __launch_bounds__(256) k_qkv(
                      const float* __restrict__ feat,
                      const float* __restrict__ Wq, const float* __restrict__ bq,
                      const float* __restrict__ Wk, const float* __restrict__ bk,
                      const float* __restrict__ Wv, const float* __restrict__ bv) {
    if (blockIdx.x == 0) {
        if (threadIdx.x < 150) g_acc[threadIdx.x] = 0.0;
        else if (threadIdx.x < 154) g_ctr[threadIdx.x - 150] = 0u;
    }
    __shared__ float sF[64][65];
    __shared__ float sW[64][64];
    const int t  = threadIdx.x;        // 256
    const int tx = t & 15;             // col group: cols 4tx..4tx+3
    const int ty = t >> 4;             // row base:  rows ty, ty+16, ty+32, ty+48
    const int rowBase = blockIdx.x * 64;
    for (int i = t; i < 4096; i += 256) sF[i>>6][i&63] = feat[rowBase*64 + i];
    __syncthreads();
    for (int m = 0; m < 3; m++) {
        const float* W    = (m==0) ? Wq : ((m==1) ? Wk : Wv);
        const float* bptr = (m==0) ? bq : ((m==1) ? bk : bv);
        float* outp       = (m==0) ? g_q : ((m==1) ? g_k : g_v);
        for (int i = t; i < 4096; i += 256) sW[i>>6][i&63] = W[i];
        __syncthreads();
        const float4 bias = *(const float4*)(bptr + 4*tx);
        float4 acc[4];
        #pragma unroll
        for (int r = 0; r < 4; r++) acc[r] = bias;
        #pragma unroll
        for (int i = 0; i < 64; i++) {
            const float4 wv = *(const float4*)&sW[i][4*tx];
            const float f0 = sF[ty     ][i];
            const float f1 = sF[ty + 16][i];
            const float f2 = sF[ty + 32][i];
            const float f3 = sF[ty + 48][i];
            acc[0].x += f0*wv.x; acc[0].y += f0*wv.y; acc[0].z += f0*wv.z; acc[0].w += f0*wv.w;
            acc[1].x += f1*wv.x; acc[1].y += f1*wv.y; acc[1].z += f1*wv.z; acc[1].w += f1*wv.w;
            acc[2].x += f2*wv.x; acc[2].y += f2*wv.y; acc[2].z += f2*wv.z; acc[2].w += f2*wv.w;
            acc[3].x += f3*wv.x; acc[3].y += f3*wv.y; acc[3].z += f3*wv.z; acc[3].w += f3*wv.w;
        }
        #pragma unroll
        for (int r = 0; r < 4; r++)
            *(float4*)&outp[(rowBase + ty + 16*r)*CC + 4*tx] = acc[r];
        __syncthreads();
    }
}

// ---------------- kernel 2: d1 = rel @ Wd1 + bd1, stats, inline d-BN fin ---
__global__ void __launch_bounds__(256) k_d1(
                     const float* __restrict__ xyz, const int* __restrict__ knn,
                     const float* __restrict__ Wd1, const float* __restrict__ bd1,
                     const float* __restrict__ gd, const float* __restrict__ bed) {
    __shared__ float red[6];
    __shared__ int sLast;
    if (threadIdx.x < 6) red[threadIdx.x] = 0.f;
    __syncthreads();
    float w[9], bb[3];
    #pragma unroll
    for (int i = 0; i < 9; i++) w[i] = Wd1[i];
    #pragma unroll
    for (int i = 0; i < 3; i++) bb[i] = bd1[i];
    float s[3] = {0,0,0}, qq[3] = {0,0,0};
    const int stride = gridDim.x * blockDim.x;
    for (int id = blockIdx.x*blockDim.x + threadIdx.x; id < ITEMS; id += stride) {
        const int p = id >> 4;
        const int b = p >> 14;
        const int n = p & (NN-1);
        const int j = knn[id];
        const float* xc = xyz + (b*NN + n)*3;
        const float* xn = xyz + (b*NN + j)*3;
        const float r0 = xc[0]-xn[0], r1 = xc[1]-xn[1], r2 = xc[2]-xn[2];
        #pragma unroll
        for (int c = 0; c < 3; c++) {
            const float d = r0*w[c] + r1*w[3+c] + r2*w[6+c] + bb[c];
            g_d1[id*3 + c] = d;
            s[c] += d; qq[c] += d*d;
        }
    }
    #pragma unroll
    for (int c = 0; c < 3; c++) {
        #pragma unroll
        for (int off = 16; off; off >>= 1) {
            s[c]  += __shfl_xor_sync(0xFFFFFFFFu, s[c],  off);
            qq[c] += __shfl_xor_sync(0xFFFFFFFFu, qq[c], off);
        }
    }
    if ((threadIdx.x & 31) == 0) {
        #pragma unroll
        for (int c = 0; c < 3; c++) {
            atomicAdd(&red[c],     s[c]);
            atomicAdd(&red[3 + c], qq[c]);
        }
    }
    __syncthreads();
    if (threadIdx.x < 6)
        atomicAdd(&g_acc[threadIdx.x], (double)red[threadIdx.x]);
    // last block finalizes d-BN into g_bn[0..5]
    if (last_block(0, threadIdx.x, &sLast)) {
        const int c = threadIdx.x;
        if (c < 3) {
            const double inv = 1.0 / (double)ITEMS;
            const double m = __ldcg(&g_acc[c])     * inv;
            const double v = __ldcg(&g_acc[3 + c]) * inv - m*m;
            const float a = gd[c] * rsqrtf((float)v + 1e-5f);
            g_bn[c]     = a;
            g_bn[3 + c] = bed[c] - (float)m * a;
        }
    }
}

// ---------------- kernel 3: attn_in compute+store + stats + g1-BN fin ------
__global__ void __launch_bounds__(256, 4) k_g1s(
                      const int* __restrict__ knn, const float* __restrict__ Wd2,
                      const float* __restrict__ bd2p,
                      const float* __restrict__ g1g, const float* __restrict__ be1) {
    __shared__ float st[8][2][16][4];
    __shared__ int   sj[8][2][16];
    __shared__ float red[128];   // [0..63]=sum per channel, [64..127]=sq
    __shared__ int   sLast;
    const int t = threadIdx.x;
    if (t < 128) red[t] = 0.f;
    __syncthreads();
    const int lane = t & 31, w = t >> 5;
    const int warp = (blockIdx.x*blockDim.x + t) >> 5;
    const int nw   = (gridDim.x*blockDim.x) >> 5;
    const int c = lane * 2;
    const float ad0=g_bn[0], ad1=g_bn[1], ad2=g_bn[2];
    const float bd0=g_bn[3], bd1v=g_bn[4], bd2v=g_bn[5];
    const float2 wr0 = *(const float2*)(Wd2 + c);
    const float2 wr1 = *(const float2*)(Wd2 + 64 + c);
    const float2 wr2 = *(const float2*)(Wd2 + 128 + c);
    const float2 bb  = *(const float2*)(bd2p + c);
    float s0=0, s1=0, q0=0, q1=0;
    int cur = 0;
    int p = warp;                       // warp < 4736 < PTS always
    if (lane < 16) {
        sj[w][0][lane] = knn[p*KK + lane];
        const float* dp = g_d1 + (p*KK + lane)*3;
        st[w][0][lane][0] = fmaxf(ad0*dp[0] + bd0,  0.f);
        st[w][0][lane][1] = fmaxf(ad1*dp[1] + bd1v, 0.f);
        st[w][0][lane][2] = fmaxf(ad2*dp[2] + bd2v, 0.f);
    }
    __syncwarp();
    while (p < PTS) {
        const int pn = p + nw;
        if (pn < PTS && lane < 16) {
            const int nb = cur ^ 1;
            sj[w][nb][lane] = knn[pn*KK + lane];
            const float* dp = g_d1 + (pn*KK + lane)*3;
            st[w][nb][lane][0] = fmaxf(ad0*dp[0] + bd0,  0.f);
            st[w][nb][lane][1] = fmaxf(ad1*dp[1] + bd1v, 0.f);
            st[w][nb][lane][2] = fmaxf(ad2*dp[2] + bd2v, 0.f);
        }
        const int b = p >> 14;
        const float2 qv = *(const float2*)(g_q + p*CC + c);
        #pragma unroll
        for (int k = 0; k < KK; k++) {
            const int j = sj[w][cur][k];
            const float t0 = st[w][cur][k][0], t1 = st[w][cur][k][1], t2 = st[w][cur][k][2];
            const float2 kr = *(const float2*)(g_k + ((b<<14) + j)*CC + c);
            const float x0 = qv.x - kr.x + t0*wr0.x + t1*wr1.x + t2*wr2.x + bb.x;
            const float x1 = qv.y - kr.y + t0*wr0.y + t1*wr1.y + t2*wr2.y + bb.y;
            *(float2*)(g_x + (p*KK + k)*CC + c) = make_float2(x0, x1);
            s0 += x0; q0 += x0*x0; s1 += x1; q1 += x1*x1;
        }
        __syncwarp();
        cur ^= 1;
        p = pn;
    }
    atomicAdd(&red[c],        s0);
    atomicAdd(&red[c + 1],    s1);
    atomicAdd(&red[64 + c],   q0);
    atomicAdd(&red[64 + c+1], q1);
    __syncthreads();
    // g_acc[6..69]=sum, g_acc[70..133]=sq  -> contiguous with red[0..127]
    if (t < 128) atomicAdd(&g_acc[6 + t], (double)red[t]);
    // last block finalizes the 64-channel g1-BN into g_bn[6..133]
    if (last_block(1, t, &sLast)) {
        if (t < 64) {
            const double inv = 1.0 / (double)ITEMS;
            const double m = __ldcg(&g_acc[6 + t])  * inv;
            const double v = __ldcg(&g_acc[70 + t]) * inv - m*m;
            const float a = g1g[t] * rsqrtf((float)v + 1e-5f);
            g_bn[6 + t]  = a;
            g_bn[70 + t] = be1[t] - (float)m * a;
        }
    }
}

// ---------------- kernel 4: h1 streaming pass + inline g2-BN finalize ------
__global__ void __launch_bounds__(256, 4) k_h1(
                     const float* __restrict__ Wg1, const float* __restrict__ bg1,
                     const float* __restrict__ g2g, const float* __restrict__ be2) {
    __shared__ float red[16];    // [0..7]=sum, [8..15]=sq
    __shared__ int   sLast;
    const int t = threadIdx.x;
    if (t < 16) red[t] = 0.f;
    __syncthreads();
    const int lane = t & 31;
    const int warp = (blockIdx.x*blockDim.x + t) >> 5;
    const int nw   = (gridDim.x*blockDim.x) >> 5;
    const int c = lane * 2;
    const float2 a1 = *(const float2*)(g_bn + 6 + c);
    const float2 b1 = *(const float2*)(g_bn + 70 + c);
    const float4 wgA0 = *(const float4*)(Wg1 + c*8);
    const float4 wgA1 = *(const float4*)(Wg1 + c*8 + 4);
    const float4 wgB0 = *(const float4*)(Wg1 + c*8 + 8);
    const float4 wgB1 = *(const float4*)(Wg1 + c*8 + 12);
    const int aOut = (lane >> 2) & 7;
    const bool isWriter = ((lane & 3) == 0);
    const float bga = bg1[aOut];
    float s2 = 0.f, q2 = 0.f;
    for (int p = warp; p < PTS; p += nw) {
        #pragma unroll
        for (int k = 0; k < KK; k++) {
            const float2 xv = *(const float2*)(g_x + (p*KK + k)*CC + c);
            const float y0 = fmaxf(a1.x*xv.x + b1.x, 0.f);
            const float y1 = fmaxf(a1.y*xv.y + b1.y, 0.f);
            float part[8];
            part[0] = y0*wgA0.x + y1*wgB0.x;
            part[1] = y0*wgA0.y + y1*wgB0.y;
            part[2] = y0*wgA0.z + y1*wgB0.z;
            part[3] = y0*wgA0.w + y1*wgB0.w;
            part[4] = y0*wgA1.x + y1*wgB1.x;
            part[5] = y0*wgA1.y + y1*wgB1.y;
            part[6] = y0*wgA1.z + y1*wgB1.z;
            part[7] = y0*wgA1.w + y1*wgB1.w;
            const float hsum = reduce8_split(part, lane);
            if (isWriter) {
                const float h = hsum + bga;
                g_h1[(p*KK + k)*AA + aOut] = h;
                s2 += h; q2 += h*h;
            }
        }
    }
    if (isWriter) {
        atomicAdd(&red[aOut],     s2);
        atomicAdd(&red[8 + aOut], q2);
    }
    __syncthreads();
    // g_acc[134..141]=sum, g_acc[142..149]=sq -> contiguous with red[0..15]
    if (t < 16) atomicAdd(&g_acc[134 + t], (double)red[t]);
    // last block finalizes the 8-channel g2-BN into g_bn[134..149]
    if (last_block(2, t, &sLast)) {
        if (t < 8) {
            const double inv = 1.0 / (double)ITEMS;
            const double m = __ldcg(&g_acc[134 + t]) * inv;
            const double v = __ldcg(&g_acc[142 + t]) * inv - m*m;
            const float a = g2g[t] * rsqrtf((float)v + 1e-5f);
            g_bn[134 + t] = a;
            g_bn[142 + t] = be2[t] - (float)m * a;
        }
    }
}

// ---------------- kernel 5: h2/softmax (32-lane staging) + aggregation -----
__global__ void __launch_bounds__(256, 4) k_final(
                        const int* __restrict__ knn, const float* __restrict__ Wd2,
                        const float* __restrict__ bd2p, const float* __restrict__ Wg2,
                        const float* __restrict__ bg2, float* __restrict__ out) {
    __shared__ float sWg2[64], sa2[8], sb2[8], sbg2[8];
    __shared__ float sattn[8][2][16][8];
    __shared__ float st[8][2][16][4];
    __shared__ int   sidx[8][2][16];
    const int t = threadIdx.x;
    if (t < 64) sWg2[t] = Wg2[t];
    if (t < 8) { sa2[t] = g_bn[134+t]; sb2[t] = g_bn[142+t]; sbg2[t] = bg2[t]; }
    __syncthreads();
    const int lane = t & 31, w = t >> 5;
    const int nw   = (gridDim.x * blockDim.x) >> 5;
    const int warp = (blockIdx.x * blockDim.x + t) >> 5;
    const int c = lane * 2;
    const float ad0=g_bn[0], ad1=g_bn[1], ad2=g_bn[2];
    const float bd0=g_bn[3], bd1v=g_bn[4], bd2v=g_bn[5];
    const float2 wr0 = *(const float2*)(Wd2 + c);
    const float2 wr1 = *(const float2*)(Wd2 + 64 + c);
    const float2 wr2 = *(const float2*)(Wd2 + 128 + c);
    const float2 bb  = *(const float2*)(bd2p + c);
    const int a = c & 7;          // even; lane covers attn indices a, a+1
    const int kk   = lane & 15;   // staging: k index
    const int half = lane >> 4;   // staging: 0 -> x 0..3, 1 -> x 4..7
    const int xb   = half * 4;

    // ---- staging lambda (all 32 lanes) ----
    auto stage = [&](int pp, int buf) {
        const int j = knn[pp*KK + kk];
        if (half == 0) sidx[w][buf][kk] = j;
        const float* hp = g_h1 + (pp*KK + kk)*AA;
        float z[8];
        #pragma unroll
        for (int x = 0; x < 8; x++) z[x] = fmaxf(sa2[x]*hp[x] + sb2[x], 0.f);
        float h2[4];
        #pragma unroll
        for (int i = 0; i < 4; i++) {
            float acc = sbg2[xb + i];
            #pragma unroll
            for (int jj = 0; jj < 8; jj++) acc += z[jj]*sWg2[jj*8 + xb + i];
            h2[i] = acc;
        }
        float mx[4];
        #pragma unroll
        for (int i = 0; i < 4; i++) mx[i] = h2[i];
        #pragma unroll
        for (int off = 8; off; off >>= 1)
            #pragma unroll
            for (int i = 0; i < 4; i++)
                mx[i] = fmaxf(mx[i], __shfl_xor_sync(0xFFFFFFFFu, mx[i], off));
        float ex[4], sm[4];
        #pragma unroll
        for (int i = 0; i < 4; i++) { ex[i] = expf(h2[i] - mx[i]); sm[i] = ex[i]; }
        #pragma unroll
        for (int off = 8; off; off >>= 1)
            #pragma unroll
            for (int i = 0; i < 4; i++)
                sm[i] += __shfl_xor_sync(0xFFFFFFFFu, sm[i], off);
        #pragma unroll
        for (int i = 0; i < 4; i++) sattn[w][buf][kk][xb + i] = ex[i] / sm[i];
        if (half == 0) {
            const float* dpp = g_d1 + (pp*KK + kk)*3;
            st[w][buf][kk][0] = fmaxf(ad0*dpp[0] + bd0,  0.f);
            st[w][buf][kk][1] = fmaxf(ad1*dpp[1] + bd1v, 0.f);
            st[w][buf][kk][2] = fmaxf(ad2*dpp[2] + bd2v, 0.f);
        }
    };

    int cur = 0;
    int p = warp;
    stage(p, 0);
    __syncwarp();
    while (p < PTS) {
        const int pn = p + nw;
        if (pn < PTS) stage(pn, cur ^ 1);
        const int b = p >> 14;
        float acc0 = 0.f, acc1 = 0.f;
        #pragma unroll
        for (int k = 0; k < KK; k++) {
            const int j = sidx[w][cur][k];
            const float2 vr = *(const float2*)(g_v + ((b<<14) + j)*CC + c);
            const float t0 = st[w][cur][k][0], t1 = st[w][cur][k][1], t2 = st[w][cur][k][2];
            const float2 at = *(const float2*)(&sattn[w][cur][k][a]);
            acc0 += (vr.x + t0*wr0.x + t1*wr1.x + t2*wr2.x + bb.x) * at.x;
            acc1 += (vr.y + t0*wr0.y + t1*wr1.y + t2*wr2.y + bb.y) * at.y;
        }
        *(float2*)(out + p*CC + c) = make_float2(acc0, acc1);
        __syncwarp();
        cur ^= 1;
        p = pn;
    }
}

// ---------------- launch ----------------------------------------------------
extern "C" void kernel_launch(void* const* d_in, const int* in_sizes, int n_in,
                              void* d_out, int out_size) {
    const float* xyz  = (const float*)d_in[0];
    const float* feat = (const float*)d_in[1];
    const int*   knn  = (const int*)  d_in[2];
    const float* Wq   = (const float*)d_in[3];  const float* bq  = (const float*)d_in[4];
    const float* Wk   = (const float*)d_in[5];  const float* bk  = (const float*)d_in[6];
    const float* Wv   = (const float*)d_in[7];  const float* bv  = (const float*)d_in[8];
    const float* Wd1  = (const float*)d_in[9];  const float* bd1 = (const float*)d_in[10];
    const float* gd   = (const float*)d_in[11]; const float* bed = (const float*)d_in[12];
    const float* Wd2  = (const float*)d_in[13]; const float* bd2 = (const float*)d_in[14];
    const float* g1   = (const float*)d_in[15]; const float* be1 = (const float*)d_in[16];
    const float* Wg1  = (const float*)d_in[17]; const float* bg1 = (const float*)d_in[18];
    const float* g2   = (const float*)d_in[19]; const float* be2 = (const float*)d_in[20];
    const float* Wg2  = (const float*)d_in[21]; const float* bg2 = (const float*)d_in[22];
    float* out = (float*)d_out;

    k_qkv   <<<512, 256>>>(feat, Wq, bq, Wk, bk, Wv, bv);
    k_d1    <<<EVEN_GRID, 256>>>(xyz, knn, Wd1, bd1, gd, bed);
    k_g1s   <<<EVEN_GRID, 256>>>(knn, Wd2, bd2, g1, be1);
    k_h1    <<<EVEN_GRID, 256>>>(Wg1, bg1, g2, be2);
    k_final <<<EVEN_GRID, 256>>>(knn, Wd2, bd2, Wg2, bg2, out);
}

// round 13
// speedup vs baseline: 1.2955x; 1.2955x over previous
#include <cuda_runtime.h>

#define BB 2
#define NN 16384
#define KK 16
#define CC 64
#define AA 8
#define PTS (BB*NN)          // 32768 points
#define ITEMS (PTS*KK)       // 524288 (b,n,k) items
#define EVEN_GRID 592        // 4 blocks * 148 SMs

// ---------------- scratch (device globals; no allocation allowed) ----------
__device__ float    g_q [PTS*CC];
__device__ float    g_k [PTS*CC];
__device__ float    g_v [PTS*CC];
__device__ float    g_d1[ITEMS*3];
__device__ float    g_h1[ITEMS*AA];
// acc layout: [0..2]=d_sum [3..5]=d_sq [6..69]=g1_sum [70..133]=g1_sq
//             [134..141]=g2_sum [142..149]=g2_sq
__device__ double   g_acc[150];
// bn layout: [0..2]=a_d [3..5]=b_d [6..69]=a1 [70..133]=b1 [134..141]=a2 [142..149]=b2
__device__ float    g_bn[150];
__device__ unsigned g_ctr[4];    // 0=d1, 1=g1s, 2=h1

// last-block detector: returns true in exactly one block, after all others
// have finished their g_acc contributions.
__device__ __forceinline__ bool last_block(int ctrId, int t, int* sFlag) {
    __syncthreads();
    if (t == 0) {
        __threadfence();
        *sFlag = (atomicAdd(&g_ctr[ctrId], 1u) == gridDim.x - 1) ? 1 : 0;
    }
    __syncthreads();
    return *sFlag != 0;
}

// ---------------- kernel 1: q/k/v linear (4x4 register-tiled GEMM) ---------
__global__ void __launch_bounds__(256) k_qkv(
                      const float* __restrict__ feat,
                      const float* __restrict__ Wq, const float* __restrict__ bq,
                      const float* __restrict__ Wk, const float* __restrict__ bk,
                      const float* __restrict__ Wv, const float* __restrict__ bv) {
    if (blockIdx.x == 0) {
        if (threadIdx.x < 150) g_acc[threadIdx.x] = 0.0;
        else if (threadIdx.x < 154) g_ctr[threadIdx.x - 150] = 0u;
    }
    __shared__ float sF[64][65];
    __shared__ float sW[64][64];
    const int t  = threadIdx.x;        // 256
    const int tx = t & 15;             // col group: cols 4tx..4tx+3
    const int ty = t >> 4;             // row base:  rows ty, ty+16, ty+32, ty+48
    const int rowBase = blockIdx.x * 64;
    for (int i = t; i < 4096; i += 256) sF[i>>6][i&63] = feat[rowBase*64 + i];
    __syncthreads();
    for (int m = 0; m < 3; m++) {
        const float* W    = (m==0) ? Wq : ((m==1) ? Wk : Wv);
        const float* bptr = (m==0) ? bq : ((m==1) ? bk : bv);
        float* outp       = (m==0) ? g_q : ((m==1) ? g_k : g_v);
        for (int i = t; i < 4096; i += 256) sW[i>>6][i&63] = W[i];
        __syncthreads();
        const float4 bias = *(const float4*)(bptr + 4*tx);
        float4 acc[4];
        #pragma unroll
        for (int r = 0; r < 4; r++) acc[r] = bias;
        #pragma unroll
        for (int i = 0; i < 64; i++) {
            const float4 wv = *(const float4*)&sW[i][4*tx];
            const float f0 = sF[ty     ][i];
            const float f1 = sF[ty + 16][i];
            const float f2 = sF[ty + 32][i];
            const float f3 = sF[ty + 48][i];
            acc[0].x += f0*wv.x; acc[0].y += f0*wv.y; acc[0].z += f0*wv.z; acc[0].w += f0*wv.w;
            acc[1].x += f1*wv.x; acc[1].y += f1*wv.y; acc[1].z += f1*wv.z; acc[1].w += f1*wv.w;
            acc[2].x += f2*wv.x; acc[2].y += f2*wv.y; acc[2].z += f2*wv.z; acc[2].w += f2*wv.w;
            acc[3].x += f3*wv.x; acc[3].y += f3*wv.y; acc[3].z += f3*wv.z; acc[3].w += f3*wv.w;
        }
        #pragma unroll
        for (int r = 0; r < 4; r++)
            *(float4*)&outp[(rowBase + ty + 16*r)*CC + 4*tx] = acc[r];
        __syncthreads();
    }
}

// ---------------- kernel 2: d1 = rel @ Wd1 + bd1, stats, inline d-BN fin ---
__global__ void __launch_bounds__(256) k_d1(
                     const float* __restrict__ xyz, const int* __restrict__ knn,
                     const float* __restrict__ Wd1, const float* __restrict__ bd1,
                     const float* __restrict__ gd, const float* __restrict__ bed) {
    __shared__ float red[6];
    __shared__ int sLast;
    if (threadIdx.x < 6) red[threadIdx.x] = 0.f;
    __syncthreads();
    float w[9], bb[3];
    #pragma unroll
    for (int i = 0; i < 9; i++) w[i] = Wd1[i];
    #pragma unroll
    for (int i = 0; i < 3; i++) bb[i] = bd1[i];
    float s[3] = {0,0,0}, qq[3] = {0,0,0};
    const int stride = gridDim.x * blockDim.x;
    for (int id = blockIdx.x*blockDim.x + threadIdx.x; id < ITEMS; id += stride) {
        const int p = id >> 4;
        const int b = p >> 14;
        const int n = p & (NN-1);
        const int j = knn[id];
        const float* xc = xyz + (b*NN + n)*3;
        const float* xn = xyz + (b*NN + j)*3;
        const float r0 = xc[0]-xn[0], r1 = xc[1]-xn[1], r2 = xc[2]-xn[2];
        #pragma unroll
        for (int c = 0; c < 3; c++) {
            const float d = r0*w[c] + r1*w[3+c] + r2*w[6+c] + bb[c];
            g_d1[id*3 + c] = d;
            s[c] += d; qq[c] += d*d;
        }
    }
    #pragma unroll
    for (int c = 0; c < 3; c++) {
        #pragma unroll
        for (int off = 16; off; off >>= 1) {
            s[c]  += __shfl_xor_sync(0xFFFFFFFFu, s[c],  off);
            qq[c] += __shfl_xor_sync(0xFFFFFFFFu, qq[c], off);
        }
    }
    if ((threadIdx.x & 31) == 0) {
        #pragma unroll
        for (int c = 0; c < 3; c++) {
            atomicAdd(&red[c],     s[c]);
            atomicAdd(&red[3 + c], qq[c]);
        }
    }
    __syncthreads();
    if (threadIdx.x < 6)
        atomicAdd(&g_acc[threadIdx.x], (double)red[threadIdx.x]);
    // last block finalizes d-BN into g_bn[0..5]
    if (last_block(0, threadIdx.x, &sLast)) {
        const int c = threadIdx.x;
        if (c < 3) {
            const double inv = 1.0 / (double)ITEMS;
            const double m = __ldcg(&g_acc[c])     * inv;
            const double v = __ldcg(&g_acc[3 + c]) * inv - m*m;
            const float a = gd[c] * rsqrtf((float)v + 1e-5f);
            g_bn[c]     = a;
            g_bn[3 + c] = bed[c] - (float)m * a;
        }
    }
}

// ---------------- kernel 3: attn_in stats + inline g1-BN finalize ----------
__global__ void __launch_bounds__(256, 4) k_g1s(
                      const int* __restrict__ knn, const float* __restrict__ Wd2,
                      const float* __restrict__ bd2p,
                      const float* __restrict__ g1g, const float* __restrict__ be1) {
    __shared__ float st[8][2][16][4];
    __shared__ int   sj[8][2][16];
    __shared__ float red[128];   // [0..63]=sum per channel, [64..127]=sq
    __shared__ int   sLast;
    const int t = threadIdx.x;
    if (t < 128) red[t] = 0.f;
    __syncthreads();
    const int lane = t & 31, w = t >> 5;
    const int warp = (blockIdx.x*blockDim.x + t) >> 5;
    const int nw   = (gridDim.x*blockDim.x) >> 5;
    const int c = lane * 2;
    const float ad0=g_bn[0], ad1=g_bn[1], ad2=g_bn[2];
    const float bd0=g_bn[3], bd1v=g_bn[4], bd2v=g_bn[5];
    const float2 wr0 = *(const float2*)(Wd2 + c);
    const float2 wr1 = *(const float2*)(Wd2 + 64 + c);
    const float2 wr2 = *(const float2*)(Wd2 + 128 + c);
    const float2 bb  = *(const float2*)(bd2p + c);
    float s0=0, s1=0, q0=0, q1=0;
    int cur = 0;
    int p = warp;                       // warp < 4736 < PTS always
    if (lane < 16) {
        sj[w][0][lane] = knn[p*KK + lane];
        const float* dp = g_d1 + (p*KK + lane)*3;
        st[w][0][lane][0] = fmaxf(ad0*dp[0] + bd0,  0.f);
        st[w][0][lane][1] = fmaxf(ad1*dp[1] + bd1v, 0.f);
        st[w][0][lane][2] = fmaxf(ad2*dp[2] + bd2v, 0.f);
    }
    __syncwarp();
    while (p < PTS) {
        const int pn = p + nw;
        if (pn < PTS && lane < 16) {
            const int nb = cur ^ 1;
            sj[w][nb][lane] = knn[pn*KK + lane];
            const float* dp = g_d1 + (pn*KK + lane)*3;
            st[w][nb][lane][0] = fmaxf(ad0*dp[0] + bd0,  0.f);
            st[w][nb][lane][1] = fmaxf(ad1*dp[1] + bd1v, 0.f);
            st[w][nb][lane][2] = fmaxf(ad2*dp[2] + bd2v, 0.f);
        }
        const int b = p >> 14;
        const float2 qv = *(const float2*)(g_q + p*CC + c);
        #pragma unroll
        for (int k = 0; k < KK; k++) {
            const int j = sj[w][cur][k];
            const float t0 = st[w][cur][k][0], t1 = st[w][cur][k][1], t2 = st[w][cur][k][2];
            const float2 kr = *(const float2*)(g_k + ((b<<14) + j)*CC + c);
            const float x0 = qv.x - kr.x + t0*wr0.x + t1*wr1.x + t2*wr2.x + bb.x;
            const float x1 = qv.y - kr.y + t0*wr0.y + t1*wr1.y + t2*wr2.y + bb.y;
            s0 += x0; q0 += x0*x0; s1 += x1; q1 += x1*x1;
        }
        __syncwarp();
        cur ^= 1;
        p = pn;
    }
    atomicAdd(&red[c],        s0);
    atomicAdd(&red[c + 1],    s1);
    atomicAdd(&red[64 + c],   q0);
    atomicAdd(&red[64 + c+1], q1);
    __syncthreads();
    // g_acc[6..69]=sum, g_acc[70..133]=sq  -> contiguous with red[0..127]
    if (t < 128) atomicAdd(&g_acc[6 + t], (double)red[t]);
    // last block finalizes the 64-channel g1-BN into g_bn[6..133]
    if (last_block(1, t, &sLast)) {
        if (t < 64) {
            const double inv = 1.0 / (double)ITEMS;
            const double m = __ldcg(&g_acc[6 + t])  * inv;
            const double v = __ldcg(&g_acc[70 + t]) * inv - m*m;
            const float a = g1g[t] * rsqrtf((float)v + 1e-5f);
            g_bn[6 + t]  = a;
            g_bn[70 + t] = be1[t] - (float)m * a;
        }
    }
}

// ---------------- kernel 4: h1 pass + inline g2-BN finalize ----------------
// Weights are loaded pre-permuted (slot i holds output aBase^i), making the
// value-splitting butterfly select-free: np[i] = part[i] + shfl(part[i+half]).
__global__ void __launch_bounds__(256, 4) k_h1(
                     const int* __restrict__ knn, const float* __restrict__ Wd2,
                     const float* __restrict__ bd2p, const float* __restrict__ Wg1,
                     const float* __restrict__ bg1,
                     const float* __restrict__ g2g, const float* __restrict__ be2) {
    __shared__ float st[8][2][16][4];
    __shared__ int   sj[8][2][16];
    __shared__ float red[16];    // [0..7]=sum, [8..15]=sq
    __shared__ int   sLast;
    const int t = threadIdx.x;
    if (t < 16) red[t] = 0.f;
    __syncthreads();
    const int lane = t & 31, w = t >> 5;
    const int warp = (blockIdx.x*blockDim.x + t) >> 5;
    const int nw   = (gridDim.x*blockDim.x) >> 5;
    const int c = lane * 2;
    const float ad0=g_bn[0], ad1=g_bn[1], ad2=g_bn[2];
    const float bd0=g_bn[3], bd1v=g_bn[4], bd2v=g_bn[5];
    const float2 wr0 = *(const float2*)(Wd2 + c);
    const float2 wr1 = *(const float2*)(Wd2 + 64 + c);
    const float2 wr2 = *(const float2*)(Wd2 + 128 + c);
    const float2 bb  = *(const float2*)(bd2p + c);
    const float2 a1  = *(const float2*)(g_bn + 6 + c);
    const float2 b1  = *(const float2*)(g_bn + 70 + c);
    const int aBase = (lane >> 2) & 7;           // output this lane ends up with
    // permuted weights: slot i <-> output (aBase ^ i)
    float wgA[8], wgB[8];
    #pragma unroll
    for (int i = 0; i < 8; i++) {
        wgA[i] = Wg1[c*8     + (aBase ^ i)];
        wgB[i] = Wg1[(c+1)*8 + (aBase ^ i)];
    }
    const bool isWriter = ((lane & 3) == 0);
    const float bga = bg1[aBase];
    float s2 = 0.f, q2 = 0.f;
    int cur = 0;
    int p = warp;
    if (lane < 16) {
        sj[w][0][lane] = knn[p*KK + lane];
        const float* dp = g_d1 + (p*KK + lane)*3;
        st[w][0][lane][0] = fmaxf(ad0*dp[0] + bd0,  0.f);
        st[w][0][lane][1] = fmaxf(ad1*dp[1] + bd1v, 0.f);
        st[w][0][lane][2] = fmaxf(ad2*dp[2] + bd2v, 0.f);
    }
    __syncwarp();
    while (p < PTS) {
        const int pn = p + nw;
        if (pn < PTS && lane < 16) {
            const int nb = cur ^ 1;
            sj[w][nb][lane] = knn[pn*KK + lane];
            const float* dp = g_d1 + (pn*KK + lane)*3;
            st[w][nb][lane][0] = fmaxf(ad0*dp[0] + bd0,  0.f);
            st[w][nb][lane][1] = fmaxf(ad1*dp[1] + bd1v, 0.f);
            st[w][nb][lane][2] = fmaxf(ad2*dp[2] + bd2v, 0.f);
        }
        const int b = p >> 14;
        const float2 qv = *(const float2*)(g_q + p*CC + c);
        #pragma unroll 8
        for (int k = 0; k < KK; k++) {
            const int j = sj[w][cur][k];
            const float t0 = st[w][cur][k][0], t1 = st[w][cur][k][1], t2 = st[w][cur][k][2];
            const float2 kr = *(const float2*)(g_k + ((b<<14) + j)*CC + c);
            const float x0 = qv.x - kr.x + t0*wr0.x + t1*wr1.x + t2*wr2.x + bb.x;
            const float x1 = qv.y - kr.y + t0*wr0.y + t1*wr1.y + t2*wr2.y + bb.y;
            const float y0 = fmaxf(a1.x*x0 + b1.x, 0.f);
            const float y1 = fmaxf(a1.y*x1 + b1.y, 0.f);
            float part[8];
            #pragma unroll
            for (int i = 0; i < 8; i++) part[i] = y0*wgA[i] + y1*wgB[i];
            // select-free value-splitting butterfly (slot i == output aBase^i)
            float np4[4];
            #pragma unroll
            for (int i = 0; i < 4; i++)
                np4[i] = part[i] + __shfl_xor_sync(0xFFFFFFFFu, part[i+4], 16);
            float np2[2];
            #pragma unroll
            for (int i = 0; i < 2; i++)
                np2[i] = np4[i] + __shfl_xor_sync(0xFFFFFFFFu, np4[i+2], 8);
            float v = np2[0] + __shfl_xor_sync(0xFFFFFFFFu, np2[1], 4);
            v += __shfl_xor_sync(0xFFFFFFFFu, v, 1);
            v += __shfl_xor_sync(0xFFFFFFFFu, v, 2);
            if (isWriter) {
                const float h = v + bga;
                g_h1[(p*KK + k)*AA + aBase] = h;
                s2 += h; q2 += h*h;
            }
        }
        __syncwarp();
        cur ^= 1;
        p = pn;
    }
    if (isWriter) {
        atomicAdd(&red[aBase],     s2);
        atomicAdd(&red[8 + aBase], q2);
    }
    __syncthreads();
    // g_acc[134..141]=sum, g_acc[142..149]=sq -> contiguous with red[0..15]
    if (t < 16) atomicAdd(&g_acc[134 + t], (double)red[t]);
    // last block finalizes the 8-channel g2-BN into g_bn[134..149]
    if (last_block(2, t, &sLast)) {
        if (t < 8) {
            const double inv = 1.0 / (double)ITEMS;
            const double m = __ldcg(&g_acc[134 + t]) * inv;
            const double v = __ldcg(&g_acc[142 + t]) * inv - m*m;
            const float a = g2g[t] * rsqrtf((float)v + 1e-5f);
            g_bn[134 + t] = a;
            g_bn[142 + t] = be2[t] - (float)m * a;
        }
    }
}

// ---------------- kernel 5: h2/softmax (32-lane staging) + aggregation -----
__global__ void __launch_bounds__(256, 4) k_final(
                        const int* __restrict__ knn, const float* __restrict__ Wd2,
                        const float* __restrict__ bd2p, const float* __restrict__ Wg2,
                        const float* __restrict__ bg2, float* __restrict__ out) {
    __shared__ float sWg2[64], sa2[8], sb2[8], sbg2[8];
    __shared__ float sattn[8][2][16][8];
    __shared__ float st[8][2][16][4];
    __shared__ int   sidx[8][2][16];
    const int t = threadIdx.x;
    if (t < 64) sWg2[t] = Wg2[t];
    if (t < 8) { sa2[t] = g_bn[134+t]; sb2[t] = g_bn[142+t]; sbg2[t] = bg2[t]; }
    __syncthreads();
    const int lane = t & 31, w = t >> 5;
    const int nw   = (gridDim.x * blockDim.x) >> 5;
    const int warp = (blockIdx.x * blockDim.x + t) >> 5;
    const int c = lane * 2;
    const float ad0=g_bn[0], ad1=g_bn[1], ad2=g_bn[2];
    const float bd0=g_bn[3], bd1v=g_bn[4], bd2v=g_bn[5];
    const float2 wr0 = *(const float2*)(Wd2 + c);
    const float2 wr1 = *(const float2*)(Wd2 + 64 + c);
    const float2 wr2 = *(const float2*)(Wd2 + 128 + c);
    const float2 bb  = *(const float2*)(bd2p + c);
    const int a = c & 7;          // even; lane covers attn indices a, a+1
    const int kk   = lane & 15;   // staging: k index
    const int half = lane >> 4;   // staging: 0 -> x 0..3, 1 -> x 4..7
    const int xb   = half * 4;

    // ---- staging lambda (all 32 lanes) ----
    auto stage = [&](int pp, int buf) {
        const int j = knn[pp*KK + kk];
        if (half == 0) sidx[w][buf][kk] = j;
        const float* hp = g_h1 + (pp*KK + kk)*AA;
        float z[8];
        #pragma unroll
        for (int x = 0; x < 8; x++) z[x] = fmaxf(sa2[x]*hp[x] + sb2[x], 0.f);
        float h2[4];
        #pragma unroll
        for (int i = 0; i < 4; i++) {
            float acc = sbg2[xb + i];
            #pragma unroll
            for (int jj = 0; jj < 8; jj++) acc += z[jj]*sWg2[jj*8 + xb + i];
            h2[i] = acc;
        }
        float mx[4];
        #pragma unroll
        for (int i = 0; i < 4; i++) mx[i] = h2[i];
        #pragma unroll
        for (int off = 8; off; off >>= 1)
            #pragma unroll
            for (int i = 0; i < 4; i++)
                mx[i] = fmaxf(mx[i], __shfl_xor_sync(0xFFFFFFFFu, mx[i], off));
        float ex[4], sm[4];
        #pragma unroll
        for (int i = 0; i < 4; i++) { ex[i] = expf(h2[i] - mx[i]); sm[i] = ex[i]; }
        #pragma unroll
        for (int off = 8; off; off >>= 1)
            #pragma unroll
            for (int i = 0; i < 4; i++)
                sm[i] += __shfl_xor_sync(0xFFFFFFFFu, sm[i], off);
        #pragma unroll
        for (int i = 0; i < 4; i++) sattn[w][buf][kk][xb + i] = ex[i] / sm[i];
        if (half == 0) {
            const float* dpp = g_d1 + (pp*KK + kk)*3;
            st[w][buf][kk][0] = fmaxf(ad0*dpp[0] + bd0,  0.f);
            st[w][buf][kk][1] = fmaxf(ad1*dpp[1] + bd1v, 0.f);
            st[w][buf][kk][2] = fmaxf(ad2*dpp[2] + bd2v, 0.f);
        }
    };

    int cur = 0;
    int p = warp;
    stage(p, 0);
    __syncwarp();
    while (p < PTS) {
        const int pn = p + nw;
        if (pn < PTS) stage(pn, cur ^ 1);
        const int b = p >> 14;
        float acc0 = 0.f, acc1 = 0.f;
        #pragma unroll
        for (int k = 0; k < KK; k++) {
            const int j = sidx[w][cur][k];
            const float2 vr = *(const float2*)(g_v + ((b<<14) + j)*CC + c);
            const float t0 = st[w][cur][k][0], t1 = st[w][cur][k][1], t2 = st[w][cur][k][2];
            const float2 at = *(const float2*)(&sattn[w][cur][k][a]);
            acc0 += (vr.x + t0*wr0.x + t1*wr1.x + t2*wr2.x + bb.x) * at.x;
            acc1 += (vr.y + t0*wr0.y + t1*wr1.y + t2*wr2.y + bb.y) * at.y;
        }
        *(float2*)(out + p*CC + c) = make_float2(acc0, acc1);
        __syncwarp();
        cur ^= 1;
        p = pn;
    }
}

// ---------------- launch ----------------------------------------------------
extern "C" void kernel_launch(void* const* d_in, const int* in_sizes, int n_in,
                              void* d_out, int out_size) {
    const float* xyz  = (const float*)d_in[0];
    const float* feat = (const float*)d_in[1];
    const int*   knn  = (const int*)  d_in[2];
    const float* Wq   = (const float*)d_in[3];  const float* bq  = (const float*)d_in[4];
    const float* Wk   = (const float*)d_in[5];  const float* bk  = (const float*)d_in[6];
    const float* Wv   = (const float*)d_in[7];  const float* bv  = (const float*)d_in[8];
    const float* Wd1  = (const float*)d_in[9];  const float* bd1 = (const float*)d_in[10];
    const float* gd   = (const float*)d_in[11]; const float* bed = (const float*)d_in[12];
    const float* Wd2  = (const float*)d_in[13]; const float* bd2 = (const float*)d_in[14];
    const float* g1   = (const float*)d_in[15]; const float* be1 = (const float*)d_in[16];
    const float* Wg1  = (const float*)d_in[17]; const float* bg1 = (const float*)d_in[18];
    const float* g2   = (const float*)d_in[19]; const float* be2 = (const float*)d_in[20];
    const float* Wg2  = (const float*)d_in[21]; const float* bg2 = (const float*)d_in[22];
    float* out = (float*)d_out;

    k_qkv   <<<512, 256>>>(feat, Wq, bq, Wk, bk, Wv, bv);
    k_d1    <<<EVEN_GRID, 256>>>(xyz, knn, Wd1, bd1, gd, bed);
    k_g1s   <<<EVEN_GRID, 256>>>(knn, Wd2, bd2, g1, be1);
    k_h1    <<<EVEN_GRID, 256>>>(knn, Wd2, bd2, Wg1, bg1, g2, be2);
    k_final <<<EVEN_GRID, 256>>>(knn, Wd2, bd2, Wg2, bg2, out);
}

// round 14
// speedup vs baseline: 1.3849x; 1.0690x over previous
#include <cuda_runtime.h>

#define BB 2
#define NN 16384
#define KK 16
#define CC 64
#define AA 8
#define PTS (BB*NN)          // 32768 points
#define ITEMS (PTS*KK)       // 524288 (b,n,k) items
#define EVEN_GRID 592        // 4 blocks * 148 SMs

// ---------------- scratch (device globals; no allocation allowed) ----------
__device__ float    g_q [PTS*CC];
__device__ float    g_k [PTS*CC];
__device__ float    g_v [PTS*CC];
__device__ float    g_d1[ITEMS*3];
__device__ float    g_h1[ITEMS*AA];
// acc layout: [0..2]=d_sum [3..5]=d_sq [6..69]=g1_sum [70..133]=g1_sq
//             [134..141]=g2_sum [142..149]=g2_sq
__device__ double   g_acc[150];
// bn layout: [0..2]=a_d [3..5]=b_d [6..69]=a1 [70..133]=b1 [134..141]=a2 [142..149]=b2
__device__ float    g_bn[150];
__device__ unsigned g_ctr[4];    // 0=d1, 1=g1s, 2=h1

// last-block detector: returns true in exactly one block, after all others
// have finished their g_acc contributions.
__device__ __forceinline__ bool last_block(int ctrId, int t, int* sFlag) {
    __syncthreads();
    if (t == 0) {
        __threadfence();
        *sFlag = (atomicAdd(&g_ctr[ctrId], 1u) == gridDim.x - 1) ? 1 : 0;
    }
    __syncthreads();
    return *sFlag != 0;
}

// ---------------- kernel 1: q/k/v linear (4x4 register-tiled GEMM) ---------
__global__ void __launch_bounds__(256) k_qkv(
                      const float* __restrict__ feat,
                      const float* __restrict__ Wq, const float* __restrict__ bq,
                      const float* __restrict__ Wk, const float* __restrict__ bk,
                      const float* __restrict__ Wv, const float* __restrict__ bv) {
    if (blockIdx.x == 0) {
        if (threadIdx.x < 150) g_acc[threadIdx.x] = 0.0;
        else if (threadIdx.x < 154) g_ctr[threadIdx.x - 150] = 0u;
    }
    __shared__ float sF[64][65];
    __shared__ float sW[64][64];
    const int t  = threadIdx.x;        // 256
    const int tx = t & 15;             // col group: cols 4tx..4tx+3
    const int ty = t >> 4;             // row base:  rows ty, ty+16, ty+32, ty+48
    const int rowBase = blockIdx.x * 64;
    for (int i = t; i < 4096; i += 256) sF[i>>6][i&63] = feat[rowBase*64 + i];
    __syncthreads();
    for (int m = 0; m < 3; m++) {
        const float* W    = (m==0) ? Wq : ((m==1) ? Wk : Wv);
        const float* bptr = (m==0) ? bq : ((m==1) ? bk : bv);
        float* outp       = (m==0) ? g_q : ((m==1) ? g_k : g_v);
        for (int i = t; i < 4096; i += 256) sW[i>>6][i&63] = W[i];
        __syncthreads();
        const float4 bias = *(const float4*)(bptr + 4*tx);
        float4 acc[4];
        #pragma unroll
        for (int r = 0; r < 4; r++) acc[r] = bias;
        #pragma unroll
        for (int i = 0; i < 64; i++) {
            const float4 wv = *(const float4*)&sW[i][4*tx];
            const float f0 = sF[ty     ][i];
            const float f1 = sF[ty + 16][i];
            const float f2 = sF[ty + 32][i];
            const float f3 = sF[ty + 48][i];
            acc[0].x += f0*wv.x; acc[0].y += f0*wv.y; acc[0].z += f0*wv.z; acc[0].w += f0*wv.w;
            acc[1].x += f1*wv.x; acc[1].y += f1*wv.y; acc[1].z += f1*wv.z; acc[1].w += f1*wv.w;
            acc[2].x += f2*wv.x; acc[2].y += f2*wv.y; acc[2].z += f2*wv.z; acc[2].w += f2*wv.w;
            acc[3].x += f3*wv.x; acc[3].y += f3*wv.y; acc[3].z += f3*wv.z; acc[3].w += f3*wv.w;
        }
        #pragma unroll
        for (int r = 0; r < 4; r++)
            *(float4*)&outp[(rowBase + ty + 16*r)*CC + 4*tx] = acc[r];
        __syncthreads();
    }
}

// ---------------- kernel 2: d1 = rel @ Wd1 + bd1, stats, inline d-BN fin ---
__global__ void __launch_bounds__(256) k_d1(
                     const float* __restrict__ xyz, const int* __restrict__ knn,
                     const float* __restrict__ Wd1, const float* __restrict__ bd1,
                     const float* __restrict__ gd, const float* __restrict__ bed) {
    __shared__ float red[6];
    __shared__ int sLast;
    if (threadIdx.x < 6) red[threadIdx.x] = 0.f;
    __syncthreads();
    float w[9], bb[3];
    #pragma unroll
    for (int i = 0; i < 9; i++) w[i] = Wd1[i];
    #pragma unroll
    for (int i = 0; i < 3; i++) bb[i] = bd1[i];
    float s[3] = {0,0,0}, qq[3] = {0,0,0};
    const int stride = gridDim.x * blockDim.x;
    for (int id = blockIdx.x*blockDim.x + threadIdx.x; id < ITEMS; id += stride) {
        const int p = id >> 4;
        const int b = p >> 14;
        const int n = p & (NN-1);
        const int j = knn[id];
        const float* xc = xyz + (b*NN + n)*3;
        const float* xn = xyz + (b*NN + j)*3;
        const float r0 = xc[0]-xn[0], r1 = xc[1]-xn[1], r2 = xc[2]-xn[2];
        #pragma unroll
        for (int c = 0; c < 3; c++) {
            const float d = r0*w[c] + r1*w[3+c] + r2*w[6+c] + bb[c];
            g_d1[id*3 + c] = d;
            s[c] += d; qq[c] += d*d;
        }
    }
    #pragma unroll
    for (int c = 0; c < 3; c++) {
        #pragma unroll
        for (int off = 16; off; off >>= 1) {
            s[c]  += __shfl_xor_sync(0xFFFFFFFFu, s[c],  off);
            qq[c] += __shfl_xor_sync(0xFFFFFFFFu, qq[c], off);
        }
    }
    if ((threadIdx.x & 31) == 0) {
        #pragma unroll
        for (int c = 0; c < 3; c++) {
            atomicAdd(&red[c],     s[c]);
            atomicAdd(&red[3 + c], qq[c]);
        }
    }
    __syncthreads();
    if (threadIdx.x < 6)
        atomicAdd(&g_acc[threadIdx.x], (double)red[threadIdx.x]);
    // last block finalizes d-BN into g_bn[0..5]
    if (last_block(0, threadIdx.x, &sLast)) {
        const int c = threadIdx.x;
        if (c < 3) {
            const double inv = 1.0 / (double)ITEMS;
            const double m = __ldcg(&g_acc[c])     * inv;
            const double v = __ldcg(&g_acc[3 + c]) * inv - m*m;
            const float a = gd[c] * rsqrtf((float)v + 1e-5f);
            g_bn[c]     = a;
            g_bn[3 + c] = bed[c] - (float)m * a;
        }
    }
}

// ---------------- kernel 3: attn_in stats + inline g1-BN finalize ----------
__global__ void __launch_bounds__(256, 4) k_g1s(
                      const int* __restrict__ knn, const float* __restrict__ Wd2,
                      const float* __restrict__ bd2p,
                      const float* __restrict__ g1g, const float* __restrict__ be1) {
    __shared__ float st[8][2][16][4];
    __shared__ int   sj[8][2][16];
    __shared__ float red[128];   // [0..63]=sum per channel, [64..127]=sq
    __shared__ int   sLast;
    const int t = threadIdx.x;
    if (t < 128) red[t] = 0.f;
    __syncthreads();
    const int lane = t & 31, w = t >> 5;
    const int warp = (blockIdx.x*blockDim.x + t) >> 5;
    const int nw   = (gridDim.x*blockDim.x) >> 5;
    const int c = lane * 2;
    const float ad0=g_bn[0], ad1=g_bn[1], ad2=g_bn[2];
    const float bd0=g_bn[3], bd1v=g_bn[4], bd2v=g_bn[5];
    const float2 wr0 = *(const float2*)(Wd2 + c);
    const float2 wr1 = *(const float2*)(Wd2 + 64 + c);
    const float2 wr2 = *(const float2*)(Wd2 + 128 + c);
    const float2 bb  = *(const float2*)(bd2p + c);
    float s0=0, s1=0, q0=0, q1=0;
    int cur = 0;
    int p = warp;                       // warp < 4736 < PTS always
    if (lane < 16) {
        sj[w][0][lane] = knn[p*KK + lane];
        const float* dp = g_d1 + (p*KK + lane)*3;
        st[w][0][lane][0] = fmaxf(ad0*dp[0] + bd0,  0.f);
        st[w][0][lane][1] = fmaxf(ad1*dp[1] + bd1v, 0.f);
        st[w][0][lane][2] = fmaxf(ad2*dp[2] + bd2v, 0.f);
    }
    __syncwarp();
    while (p < PTS) {
        const int pn = p + nw;
        if (pn < PTS && lane < 16) {
            const int nb = cur ^ 1;
            sj[w][nb][lane] = knn[pn*KK + lane];
            const float* dp = g_d1 + (pn*KK + lane)*3;
            st[w][nb][lane][0] = fmaxf(ad0*dp[0] + bd0,  0.f);
            st[w][nb][lane][1] = fmaxf(ad1*dp[1] + bd1v, 0.f);
            st[w][nb][lane][2] = fmaxf(ad2*dp[2] + bd2v, 0.f);
        }
        const int b = p >> 14;
        const float2 qv = *(const float2*)(g_q + p*CC + c);
        #pragma unroll
        for (int k = 0; k < KK; k++) {
            const int j = sj[w][cur][k];
            const float t0 = st[w][cur][k][0], t1 = st[w][cur][k][1], t2 = st[w][cur][k][2];
            const float2 kr = *(const float2*)(g_k + ((b<<14) + j)*CC + c);
            const float x0 = qv.x - kr.x + t0*wr0.x + t1*wr1.x + t2*wr2.x + bb.x;
            const float x1 = qv.y - kr.y + t0*wr0.y + t1*wr1.y + t2*wr2.y + bb.y;
            s0 += x0; q0 += x0*x0; s1 += x1; q1 += x1*x1;
        }
        __syncwarp();
        cur ^= 1;
        p = pn;
    }
    atomicAdd(&red[c],        s0);
    atomicAdd(&red[c + 1],    s1);
    atomicAdd(&red[64 + c],   q0);
    atomicAdd(&red[64 + c+1], q1);
    __syncthreads();
    // g_acc[6..69]=sum, g_acc[70..133]=sq  -> contiguous with red[0..127]
    if (t < 128) atomicAdd(&g_acc[6 + t], (double)red[t]);
    // last block finalizes the 64-channel g1-BN into g_bn[6..133]
    if (last_block(1, t, &sLast)) {
        if (t < 64) {
            const double inv = 1.0 / (double)ITEMS;
            const double m = __ldcg(&g_acc[6 + t])  * inv;
            const double v = __ldcg(&g_acc[70 + t]) * inv - m*m;
            const float a = g1g[t] * rsqrtf((float)v + 1e-5f);
            g_bn[6 + t]  = a;
            g_bn[70 + t] = be1[t] - (float)m * a;
        }
    }
}

// ---------------- kernel 4: h1 pass + inline g2-BN finalize ----------------
// g1-BN affine folded into constants: y = max(fma(-a1,kr,qp) + sum t_d*wr'_d, 0)
// Weights pre-permuted (slot i holds output aBase^i) -> select-free butterfly.
__global__ void __launch_bounds__(256, 4) k_h1(
                     const int* __restrict__ knn, const float* __restrict__ Wd2,
                     const float* __restrict__ bd2p, const float* __restrict__ Wg1,
                     const float* __restrict__ bg1,
                     const float* __restrict__ g2g, const float* __restrict__ be2) {
    __shared__ float st[8][2][16][4];
    __shared__ int   sj[8][2][16];
    __shared__ float red[16];    // [0..7]=sum, [8..15]=sq
    __shared__ int   sLast;
    const int t = threadIdx.x;
    if (t < 16) red[t] = 0.f;
    __syncthreads();
    const int lane = t & 31, w = t >> 5;
    const int warp = (blockIdx.x*blockDim.x + t) >> 5;
    const int nw   = (gridDim.x*blockDim.x) >> 5;
    const int c = lane * 2;
    const float ad0=g_bn[0], ad1=g_bn[1], ad2=g_bn[2];
    const float bd0=g_bn[3], bd1v=g_bn[4], bd2v=g_bn[5];
    const float2 a1  = *(const float2*)(g_bn + 6 + c);
    const float2 b1  = *(const float2*)(g_bn + 70 + c);
    // fold a1 into pos-enc weights and bias
    const float2 wr0r = *(const float2*)(Wd2 + c);
    const float2 wr1r = *(const float2*)(Wd2 + 64 + c);
    const float2 wr2r = *(const float2*)(Wd2 + 128 + c);
    const float2 bbr  = *(const float2*)(bd2p + c);
    const float2 wr0 = make_float2(a1.x*wr0r.x, a1.y*wr0r.y);
    const float2 wr1 = make_float2(a1.x*wr1r.x, a1.y*wr1r.y);
    const float2 wr2 = make_float2(a1.x*wr2r.x, a1.y*wr2r.y);
    const float2 bbf = make_float2(a1.x*bbr.x + b1.x, a1.y*bbr.y + b1.y);
    const float2 na1 = make_float2(-a1.x, -a1.y);
    const int aBase = (lane >> 2) & 7;           // output this lane ends up with
    // permuted weights: slot i <-> output (aBase ^ i)
    float wgA[8], wgB[8];
    #pragma unroll
    for (int i = 0; i < 8; i++) {
        wgA[i] = Wg1[c*8     + (aBase ^ i)];
        wgB[i] = Wg1[(c+1)*8 + (aBase ^ i)];
    }
    const bool isWriter = ((lane & 3) == 0);
    const float bga = bg1[aBase];
    float s2 = 0.f, q2 = 0.f;
    int cur = 0;
    int p = warp;
    if (lane < 16) {
        sj[w][0][lane] = knn[p*KK + lane];
        const float* dp = g_d1 + (p*KK + lane)*3;
        st[w][0][lane][0] = fmaxf(ad0*dp[0] + bd0,  0.f);
        st[w][0][lane][1] = fmaxf(ad1*dp[1] + bd1v, 0.f);
        st[w][0][lane][2] = fmaxf(ad2*dp[2] + bd2v, 0.f);
    }
    __syncwarp();
    while (p < PTS) {
        const int pn = p + nw;
        if (pn < PTS && lane < 16) {
            const int nb = cur ^ 1;
            sj[w][nb][lane] = knn[pn*KK + lane];
            const float* dp = g_d1 + (pn*KK + lane)*3;
            st[w][nb][lane][0] = fmaxf(ad0*dp[0] + bd0,  0.f);
            st[w][nb][lane][1] = fmaxf(ad1*dp[1] + bd1v, 0.f);
            st[w][nb][lane][2] = fmaxf(ad2*dp[2] + bd2v, 0.f);
        }
        const int b = p >> 14;
        const float2 qv = *(const float2*)(g_q + p*CC + c);
        // per-point folded q: qp = a1*q + bbf
        const float2 qp = make_float2(a1.x*qv.x + bbf.x, a1.y*qv.y + bbf.y);
        #pragma unroll 8
        for (int k = 0; k < KK; k++) {
            const int j = sj[w][cur][k];
            const float t0 = st[w][cur][k][0], t1 = st[w][cur][k][1], t2 = st[w][cur][k][2];
            const float2 kr = *(const float2*)(g_k + ((b<<14) + j)*CC + c);
            float y0 = fmaf(na1.x, kr.x, qp.x);
            float y1 = fmaf(na1.y, kr.y, qp.y);
            y0 = fmaf(t0, wr0.x, y0); y1 = fmaf(t0, wr0.y, y1);
            y0 = fmaf(t1, wr1.x, y0); y1 = fmaf(t1, wr1.y, y1);
            y0 = fmaf(t2, wr2.x, y0); y1 = fmaf(t2, wr2.y, y1);
            y0 = fmaxf(y0, 0.f);
            y1 = fmaxf(y1, 0.f);
            float part[8];
            #pragma unroll
            for (int i = 0; i < 8; i++) part[i] = y0*wgA[i] + y1*wgB[i];
            // select-free value-splitting butterfly (slot i == output aBase^i)
            float np4[4];
            #pragma unroll
            for (int i = 0; i < 4; i++)
                np4[i] = part[i] + __shfl_xor_sync(0xFFFFFFFFu, part[i+4], 16);
            float np2[2];
            #pragma unroll
            for (int i = 0; i < 2; i++)
                np2[i] = np4[i] + __shfl_xor_sync(0xFFFFFFFFu, np4[i+2], 8);
            float v = np2[0] + __shfl_xor_sync(0xFFFFFFFFu, np2[1], 4);
            v += __shfl_xor_sync(0xFFFFFFFFu, v, 1);
            v += __shfl_xor_sync(0xFFFFFFFFu, v, 2);
            if (isWriter) {
                const float h = v + bga;
                g_h1[(p*KK + k)*AA + aBase] = h;
                s2 += h; q2 += h*h;
            }
        }
        __syncwarp();
        cur ^= 1;
        p = pn;
    }
    if (isWriter) {
        atomicAdd(&red[aBase],     s2);
        atomicAdd(&red[8 + aBase], q2);
    }
    __syncthreads();
    // g_acc[134..141]=sum, g_acc[142..149]=sq -> contiguous with red[0..15]
    if (t < 16) atomicAdd(&g_acc[134 + t], (double)red[t]);
    // last block finalizes the 8-channel g2-BN into g_bn[134..149]
    if (last_block(2, t, &sLast)) {
        if (t < 8) {
            const double inv = 1.0 / (double)ITEMS;
            const double m = __ldcg(&g_acc[134 + t]) * inv;
            const double v = __ldcg(&g_acc[142 + t]) * inv - m*m;
            const float a = g2g[t] * rsqrtf((float)v + 1e-5f);
            g_bn[134 + t] = a;
            g_bn[142 + t] = be2[t] - (float)m * a;
        }
    }
}

// ---------------- kernel 5: h2/softmax (32-lane staging) + aggregation -----
__global__ void __launch_bounds__(256, 4) k_final(
                        const int* __restrict__ knn, const float* __restrict__ Wd2,
                        const float* __restrict__ bd2p, const float* __restrict__ Wg2,
                        const float* __restrict__ bg2, float* __restrict__ out) {
    __shared__ float sWg2[64], sa2[8], sb2[8], sbg2[8];
    __shared__ float sattn[8][2][16][8];
    __shared__ float st[8][2][16][4];
    __shared__ int   sidx[8][2][16];
    const int t = threadIdx.x;
    if (t < 64) sWg2[t] = Wg2[t];
    if (t < 8) { sa2[t] = g_bn[134+t]; sb2[t] = g_bn[142+t]; sbg2[t] = bg2[t]; }
    __syncthreads();
    const int lane = t & 31, w = t >> 5;
    const int nw   = (gridDim.x * blockDim.x) >> 5;
    const int warp = (blockIdx.x * blockDim.x + t) >> 5;
    const int c = lane * 2;
    const float ad0=g_bn[0], ad1=g_bn[1], ad2=g_bn[2];
    const float bd0=g_bn[3], bd1v=g_bn[4], bd2v=g_bn[5];
    const float2 wr0 = *(const float2*)(Wd2 + c);
    const float2 wr1 = *(const float2*)(Wd2 + 64 + c);
    const float2 wr2 = *(const float2*)(Wd2 + 128 + c);
    const float2 bb  = *(const float2*)(bd2p + c);
    const int a = c & 7;          // even; lane covers attn indices a, a+1
    const int kk   = lane & 15;   // staging: k index
    const int half = lane >> 4;   // staging: 0 -> x 0..3, 1 -> x 4..7
    const int xb   = half * 4;

    // ---- staging lambda (all 32 lanes) ----
    auto stage = [&](int pp, int buf) {
        const int j = knn[pp*KK + kk];
        if (half == 0) sidx[w][buf][kk] = j;
        const float* hp = g_h1 + (pp*KK + kk)*AA;
        float z[8];
        #pragma unroll
        for (int x = 0; x < 8; x++) z[x] = fmaxf(sa2[x]*hp[x] + sb2[x], 0.f);
        float h2[4];
        #pragma unroll
        for (int i = 0; i < 4; i++) {
            float acc = sbg2[xb + i];
            #pragma unroll
            for (int jj = 0; jj < 8; jj++) acc += z[jj]*sWg2[jj*8 + xb + i];
            h2[i] = acc;
        }
        float mx[4];
        #pragma unroll
        for (int i = 0; i < 4; i++) mx[i] = h2[i];
        #pragma unroll
        for (int off = 8; off; off >>= 1)
            #pragma unroll
            for (int i = 0; i < 4; i++)
                mx[i] = fmaxf(mx[i], __shfl_xor_sync(0xFFFFFFFFu, mx[i], off));
        float ex[4], sm[4];
        #pragma unroll
        for (int i = 0; i < 4; i++) { ex[i] = __expf(h2[i] - mx[i]); sm[i] = ex[i]; }
        #pragma unroll
        for (int off = 8; off; off >>= 1)
            #pragma unroll
            for (int i = 0; i < 4; i++)
                sm[i] += __shfl_xor_sync(0xFFFFFFFFu, sm[i], off);
        #pragma unroll
        for (int i = 0; i < 4; i++) sattn[w][buf][kk][xb + i] = __fdividef(ex[i], sm[i]);
        if (half == 0) {
            const float* dpp = g_d1 + (pp*KK + kk)*3;
            st[w][buf][kk][0] = fmaxf(ad0*dpp[0] + bd0,  0.f);
            st[w][buf][kk][1] = fmaxf(ad1*dpp[1] + bd1v, 0.f);
            st[w][buf][kk][2] = fmaxf(ad2*dpp[2] + bd2v, 0.f);
        }
    };

    int cur = 0;
    int p = warp;
    stage(p, 0);
    __syncwarp();
    while (p < PTS) {
        const int pn = p + nw;
        if (pn < PTS) stage(pn, cur ^ 1);
        const int b = p >> 14;
        float acc0 = 0.f, acc1 = 0.f;
        #pragma unroll
        for (int k = 0; k < KK; k++) {
            const int j = sidx[w][cur][k];
            const float2 vr = *(const float2*)(g_v + ((b<<14) + j)*CC + c);
            const float t0 = st[w][cur][k][0], t1 = st[w][cur][k][1], t2 = st[w][cur][k][2];
            const float2 at = *(const float2*)(&sattn[w][cur][k][a]);
            acc0 += (vr.x + t0*wr0.x + t1*wr1.x + t2*wr2.x + bb.x) * at.x;
            acc1 += (vr.y + t0*wr0.y + t1*wr1.y + t2*wr2.y + bb.y) * at.y;
        }
        *(float2*)(out + p*CC + c) = make_float2(acc0, acc1);
        __syncwarp();
        cur ^= 1;
        p = pn;
    }
}

// ---------------- launch ----------------------------------------------------
extern "C" void kernel_launch(void* const* d_in, const int* in_sizes, int n_in,
                              void* d_out, int out_size) {
    const float* xyz  = (const float*)d_in[0];
    const float* feat = (const float*)d_in[1];
    const int*   knn  = (const int*)  d_in[2];
    const float* Wq   = (const float*)d_in[3];  const float* bq  = (const float*)d_in[4];
    const float* Wk   = (const float*)d_in[5];  const float* bk  = (const float*)d_in[6];
    const float* Wv   = (const float*)d_in[7];  const float* bv  = (const float*)d_in[8];
    const float* Wd1  = (const float*)d_in[9];  const float* bd1 = (const float*)d_in[10];
    const float* gd   = (const float*)d_in[11]; const float* bed = (const float*)d_in[12];
    const float* Wd2  = (const float*)d_in[13]; const float* bd2 = (const float*)d_in[14];
    const float* g1   = (const float*)d_in[15]; const float* be1 = (const float*)d_in[16];
    const float* Wg1  = (const float*)d_in[17]; const float* bg1 = (const float*)d_in[18];
    const float* g2   = (const float*)d_in[19]; const float* be2 = (const float*)d_in[20];
    const float* Wg2  = (const float*)d_in[21]; const float* bg2 = (const float*)d_in[22];
    float* out = (float*)d_out;

    k_qkv   <<<512, 256>>>(feat, Wq, bq, Wk, bk, Wv, bv);
    k_d1    <<<EVEN_GRID, 256>>>(xyz, knn, Wd1, bd1, gd, bed);
    k_g1s   <<<EVEN_GRID, 256>>>(knn, Wd2, bd2, g1, be1);
    k_h1    <<<EVEN_GRID, 256>>>(knn, Wd2, bd2, Wg1, bg1, g2, be2);
    k_final <<<EVEN_GRID, 256>>>(knn, Wd2, bd2, Wg2, bg2, out);
}

// round 15
// speedup vs baseline: 1.3879x; 1.0022x over previous
#include <cuda_runtime.h>

#define BB 2
#define NN 16384
#define KK 16
#define CC 64
#define AA 8
#define PTS (BB*NN)          // 32768 points
#define ITEMS (PTS*KK)       // 524288 (b,n,k) items
#define EVEN_GRID 592        // 4 blocks * 148 SMs

// ---------------- scratch (device globals; no allocation allowed) ----------
__device__ float    g_q [PTS*CC];
__device__ float    g_k [PTS*CC];
__device__ float    g_v [PTS*CC];
__device__ float    g_d1[ITEMS*3];
__device__ float    g_h1[ITEMS*AA];
// acc layout: [0..2]=d_sum [3..5]=d_sq [6..69]=g1_sum [70..133]=g1_sq
//             [134..141]=g2_sum [142..149]=g2_sq
__device__ double   g_acc[150];
// bn layout: [0..2]=a_d [3..5]=b_d [6..69]=a1 [70..133]=b1 [134..141]=a2 [142..149]=b2
__device__ float    g_bn[150];
__device__ unsigned g_ctr[4];    // 0=d1, 1=g1s, 2=h1

// last-block detector: returns true in exactly one block, after all others
// have finished their g_acc contributions.
__device__ __forceinline__ bool last_block(int ctrId, int t, int* sFlag) {
    __syncthreads();
    if (t == 0) {
        __threadfence();
        *sFlag = (atomicAdd(&g_ctr[ctrId], 1u) == gridDim.x - 1) ? 1 : 0;
    }
    __syncthreads();
    return *sFlag != 0;
}

// ---------------- kernel 1: q/k/v linear (4x4 register-tiled GEMM) ---------
__global__ void __launch_bounds__(256) k_qkv(
                      const float* __restrict__ feat,
                      const float* __restrict__ Wq, const float* __restrict__ bq,
                      const float* __restrict__ Wk, const float* __restrict__ bk,
                      const float* __restrict__ Wv, const float* __restrict__ bv) {
    if (blockIdx.x == 0) {
        if (threadIdx.x < 150) g_acc[threadIdx.x] = 0.0;
        else if (threadIdx.x < 154) g_ctr[threadIdx.x - 150] = 0u;
    }
    __shared__ float sF[64][65];
    __shared__ float sW[64][64];
    const int t  = threadIdx.x;        // 256
    const int tx = t & 15;             // col group: cols 4tx..4tx+3
    const int ty = t >> 4;             // row base:  rows ty, ty+16, ty+32, ty+48
    const int rowBase = blockIdx.x * 64;
    for (int i = t; i < 4096; i += 256) sF[i>>6][i&63] = feat[rowBase*64 + i];
    __syncthreads();
    for (int m = 0; m < 3; m++) {
        const float* W    = (m==0) ? Wq : ((m==1) ? Wk : Wv);
        const float* bptr = (m==0) ? bq : ((m==1) ? bk : bv);
        float* outp       = (m==0) ? g_q : ((m==1) ? g_k : g_v);
        for (int i = t; i < 4096; i += 256) sW[i>>6][i&63] = W[i];
        __syncthreads();
        const float4 bias = *(const float4*)(bptr + 4*tx);
        float4 acc[4];
        #pragma unroll
        for (int r = 0; r < 4; r++) acc[r] = bias;
        #pragma unroll
        for (int i = 0; i < 64; i++) {
            const float4 wv = *(const float4*)&sW[i][4*tx];
            const float f0 = sF[ty     ][i];
            const float f1 = sF[ty + 16][i];
            const float f2 = sF[ty + 32][i];
            const float f3 = sF[ty + 48][i];
            acc[0].x += f0*wv.x; acc[0].y += f0*wv.y; acc[0].z += f0*wv.z; acc[0].w += f0*wv.w;
            acc[1].x += f1*wv.x; acc[1].y += f1*wv.y; acc[1].z += f1*wv.z; acc[1].w += f1*wv.w;
            acc[2].x += f2*wv.x; acc[2].y += f2*wv.y; acc[2].z += f2*wv.z; acc[2].w += f2*wv.w;
            acc[3].x += f3*wv.x; acc[3].y += f3*wv.y; acc[3].z += f3*wv.z; acc[3].w += f3*wv.w;
        }
        #pragma unroll
        for (int r = 0; r < 4; r++)
            *(float4*)&outp[(rowBase + ty + 16*r)*CC + 4*tx] = acc[r];
        __syncthreads();
    }
}

// ---------------- kernel 2: d1 = rel @ Wd1 + bd1, stats, inline d-BN fin ---
__global__ void __launch_bounds__(256) k_d1(
                     const float* __restrict__ xyz, const int* __restrict__ knn,
                     const float* __restrict__ Wd1, const float* __restrict__ bd1,
                     const float* __restrict__ gd, const float* __restrict__ bed) {
    __shared__ float red[6];
    __shared__ int sLast;
    if (threadIdx.x < 6) red[threadIdx.x] = 0.f;
    __syncthreads();
    float w[9], bb[3];
    #pragma unroll
    for (int i = 0; i < 9; i++) w[i] = Wd1[i];
    #pragma unroll
    for (int i = 0; i < 3; i++) bb[i] = bd1[i];
    float s[3] = {0,0,0}, qq[3] = {0,0,0};
    const int stride = gridDim.x * blockDim.x;
    for (int id = blockIdx.x*blockDim.x + threadIdx.x; id < ITEMS; id += stride) {
        const int p = id >> 4;
        const int b = p >> 14;
        const int n = p & (NN-1);
        const int j = knn[id];
        const float* xc = xyz + (b*NN + n)*3;
        const float* xn = xyz + (b*NN + j)*3;
        const float r0 = xc[0]-xn[0], r1 = xc[1]-xn[1], r2 = xc[2]-xn[2];
        #pragma unroll
        for (int c = 0; c < 3; c++) {
            const float d = r0*w[c] + r1*w[3+c] + r2*w[6+c] + bb[c];
            g_d1[id*3 + c] = d;
            s[c] += d; qq[c] += d*d;
        }
    }
    #pragma unroll
    for (int c = 0; c < 3; c++) {
        #pragma unroll
        for (int off = 16; off; off >>= 1) {
            s[c]  += __shfl_xor_sync(0xFFFFFFFFu, s[c],  off);
            qq[c] += __shfl_xor_sync(0xFFFFFFFFu, qq[c], off);
        }
    }
    if ((threadIdx.x & 31) == 0) {
        #pragma unroll
        for (int c = 0; c < 3; c++) {
            atomicAdd(&red[c],     s[c]);
            atomicAdd(&red[3 + c], qq[c]);
        }
    }
    __syncthreads();
    if (threadIdx.x < 6)
        atomicAdd(&g_acc[threadIdx.x], (double)red[threadIdx.x]);
    // last block finalizes d-BN into g_bn[0..5]
    if (last_block(0, threadIdx.x, &sLast)) {
        const int c = threadIdx.x;
        if (c < 3) {
            const double inv = 1.0 / (double)ITEMS;
            const double m = __ldcg(&g_acc[c])     * inv;
            const double v = __ldcg(&g_acc[3 + c]) * inv - m*m;
            const float a = gd[c] * rsqrtf((float)v + 1e-5f);
            g_bn[c]     = a;
            g_bn[3 + c] = bed[c] - (float)m * a;
        }
    }
}

// ---------------- kernel 3: attn_in stats + inline g1-BN finalize ----------
__global__ void __launch_bounds__(256, 4) k_g1s(
                      const int* __restrict__ knn, const float* __restrict__ Wd2,
                      const float* __restrict__ bd2p,
                      const float* __restrict__ g1g, const float* __restrict__ be1) {
    __shared__ float st[8][2][16][4];
    __shared__ int   sj[8][2][16];
    __shared__ float red[128];   // [0..63]=sum per channel, [64..127]=sq
    __shared__ int   sLast;
    const int t = threadIdx.x;
    if (t < 128) red[t] = 0.f;
    __syncthreads();
    const int lane = t & 31, w = t >> 5;
    const int warp = (blockIdx.x*blockDim.x + t) >> 5;
    const int nw   = (gridDim.x*blockDim.x) >> 5;
    const int c = lane * 2;
    const float ad0=g_bn[0], ad1=g_bn[1], ad2=g_bn[2];
    const float bd0=g_bn[3], bd1v=g_bn[4], bd2v=g_bn[5];
    const float2 wr0 = *(const float2*)(Wd2 + c);
    const float2 wr1 = *(const float2*)(Wd2 + 64 + c);
    const float2 wr2 = *(const float2*)(Wd2 + 128 + c);
    const float2 bb  = *(const float2*)(bd2p + c);
    float s0=0, s1=0, q0=0, q1=0;
    int cur = 0;
    int p = warp;                       // warp < 4736 < PTS always
    if (lane < 16) {
        sj[w][0][lane] = knn[p*KK + lane];
        const float* dp = g_d1 + (p*KK + lane)*3;
        st[w][0][lane][0] = fmaxf(ad0*dp[0] + bd0,  0.f);
        st[w][0][lane][1] = fmaxf(ad1*dp[1] + bd1v, 0.f);
        st[w][0][lane][2] = fmaxf(ad2*dp[2] + bd2v, 0.f);
    }
    __syncwarp();
    while (p < PTS) {
        const int pn = p + nw;
        if (pn < PTS && lane < 16) {
            const int nb = cur ^ 1;
            sj[w][nb][lane] = knn[pn*KK + lane];
            const float* dp = g_d1 + (pn*KK + lane)*3;
            st[w][nb][lane][0] = fmaxf(ad0*dp[0] + bd0,  0.f);
            st[w][nb][lane][1] = fmaxf(ad1*dp[1] + bd1v, 0.f);
            st[w][nb][lane][2] = fmaxf(ad2*dp[2] + bd2v, 0.f);
        }
        const int b = p >> 14;
        const float2 qv = *(const float2*)(g_q + p*CC + c);
        #pragma unroll
        for (int k = 0; k < KK; k++) {
            const int j = sj[w][cur][k];
            const float t0 = st[w][cur][k][0], t1 = st[w][cur][k][1], t2 = st[w][cur][k][2];
            const float2 kr = *(const float2*)(g_k + ((b<<14) + j)*CC + c);
            const float x0 = qv.x - kr.x + t0*wr0.x + t1*wr1.x + t2*wr2.x + bb.x;
            const float x1 = qv.y - kr.y + t0*wr0.y + t1*wr1.y + t2*wr2.y + bb.y;
            s0 += x0; q0 += x0*x0; s1 += x1; q1 += x1*x1;
        }
        __syncwarp();
        cur ^= 1;
        p = pn;
    }
    atomicAdd(&red[c],        s0);
    atomicAdd(&red[c + 1],    s1);
    atomicAdd(&red[64 + c],   q0);
    atomicAdd(&red[64 + c+1], q1);
    __syncthreads();
    // g_acc[6..69]=sum, g_acc[70..133]=sq  -> contiguous with red[0..127]
    if (t < 128) atomicAdd(&g_acc[6 + t], (double)red[t]);
    // last block finalizes the 64-channel g1-BN into g_bn[6..133]
    if (last_block(1, t, &sLast)) {
        if (t < 64) {
            const double inv = 1.0 / (double)ITEMS;
            const double m = __ldcg(&g_acc[6 + t])  * inv;
            const double v = __ldcg(&g_acc[70 + t]) * inv - m*m;
            const float a = g1g[t] * rsqrtf((float)v + 1e-5f);
            g_bn[6 + t]  = a;
            g_bn[70 + t] = be1[t] - (float)m * a;
        }
    }
}

// ---------------- kernel 4: h1 pass + inline g2-BN finalize ----------------
// g1-BN affine folded into constants: y = max(fma(-a1,kr,qp) + sum t_d*wr'_d, 0)
// Weights pre-permuted (slot i holds output aBase^i) -> select-free butterfly.
__global__ void __launch_bounds__(256, 4) k_h1(
                     const int* __restrict__ knn, const float* __restrict__ Wd2,
                     const float* __restrict__ bd2p, const float* __restrict__ Wg1,
                     const float* __restrict__ bg1,
                     const float* __restrict__ g2g, const float* __restrict__ be2) {
    __shared__ float st[8][2][16][4];
    __shared__ int   sj[8][2][16];
    __shared__ float red[16];    // [0..7]=sum, [8..15]=sq
    __shared__ int   sLast;
    const int t = threadIdx.x;
    if (t < 16) red[t] = 0.f;
    __syncthreads();
    const int lane = t & 31, w = t >> 5;
    const int warp = (blockIdx.x*blockDim.x + t) >> 5;
    const int nw   = (gridDim.x*blockDim.x) >> 5;
    const int c = lane * 2;
    const float ad0=g_bn[0], ad1=g_bn[1], ad2=g_bn[2];
    const float bd0=g_bn[3], bd1v=g_bn[4], bd2v=g_bn[5];
    const float2 a1  = *(const float2*)(g_bn + 6 + c);
    const float2 b1  = *(const float2*)(g_bn + 70 + c);
    // fold a1 into pos-enc weights and bias
    const float2 wr0r = *(const float2*)(Wd2 + c);
    const float2 wr1r = *(const float2*)(Wd2 + 64 + c);
    const float2 wr2r = *(const float2*)(Wd2 + 128 + c);
    const float2 bbr  = *(const float2*)(bd2p + c);
    const float2 wr0 = make_float2(a1.x*wr0r.x, a1.y*wr0r.y);
    const float2 wr1 = make_float2(a1.x*wr1r.x, a1.y*wr1r.y);
    const float2 wr2 = make_float2(a1.x*wr2r.x, a1.y*wr2r.y);
    const float2 bbf = make_float2(a1.x*bbr.x + b1.x, a1.y*bbr.y + b1.y);
    const float2 na1 = make_float2(-a1.x, -a1.y);
    const int aBase = (lane >> 2) & 7;           // output this lane ends up with
    // permuted weights: slot i <-> output (aBase ^ i)
    float wgA[8], wgB[8];
    #pragma unroll
    for (int i = 0; i < 8; i++) {
        wgA[i] = Wg1[c*8     + (aBase ^ i)];
        wgB[i] = Wg1[(c+1)*8 + (aBase ^ i)];
    }
    const bool isWriter = ((lane & 3) == 0);
    const float bga = bg1[aBase];
    float s2 = 0.f, q2 = 0.f;
    int cur = 0;
    int p = warp;
    if (lane < 16) {
        sj[w][0][lane] = knn[p*KK + lane];
        const float* dp = g_d1 + (p*KK + lane)*3;
        st[w][0][lane][0] = fmaxf(ad0*dp[0] + bd0,  0.f);
        st[w][0][lane][1] = fmaxf(ad1*dp[1] + bd1v, 0.f);
        st[w][0][lane][2] = fmaxf(ad2*dp[2] + bd2v, 0.f);
    }
    __syncwarp();
    while (p < PTS) {
        const int pn = p + nw;
        if (pn < PTS && lane < 16) {
            const int nb = cur ^ 1;
            sj[w][nb][lane] = knn[pn*KK + lane];
            const float* dp = g_d1 + (pn*KK + lane)*3;
            st[w][nb][lane][0] = fmaxf(ad0*dp[0] + bd0,  0.f);
            st[w][nb][lane][1] = fmaxf(ad1*dp[1] + bd1v, 0.f);
            st[w][nb][lane][2] = fmaxf(ad2*dp[2] + bd2v, 0.f);
        }
        const int b = p >> 14;
        const float2 qv = *(const float2*)(g_q + p*CC + c);
        // per-point folded q: qp = a1*q + bbf
        const float2 qp = make_float2(a1.x*qv.x + bbf.x, a1.y*qv.y + bbf.y);
        #pragma unroll 8
        for (int k = 0; k < KK; k++) {
            const int j = sj[w][cur][k];
            const float t0 = st[w][cur][k][0], t1 = st[w][cur][k][1], t2 = st[w][cur][k][2];
            const float2 kr = *(const float2*)(g_k + ((b<<14) + j)*CC + c);
            float y0 = fmaf(na1.x, kr.x, qp.x);
            float y1 = fmaf(na1.y, kr.y, qp.y);
            y0 = fmaf(t0, wr0.x, y0); y1 = fmaf(t0, wr0.y, y1);
            y0 = fmaf(t1, wr1.x, y0); y1 = fmaf(t1, wr1.y, y1);
            y0 = fmaf(t2, wr2.x, y0); y1 = fmaf(t2, wr2.y, y1);
            y0 = fmaxf(y0, 0.f);
            y1 = fmaxf(y1, 0.f);
            float part[8];
            #pragma unroll
            for (int i = 0; i < 8; i++) part[i] = y0*wgA[i] + y1*wgB[i];
            // select-free value-splitting butterfly (slot i == output aBase^i)
            float np4[4];
            #pragma unroll
            for (int i = 0; i < 4; i++)
                np4[i] = part[i] + __shfl_xor_sync(0xFFFFFFFFu, part[i+4], 16);
            float np2[2];
            #pragma unroll
            for (int i = 0; i < 2; i++)
                np2[i] = np4[i] + __shfl_xor_sync(0xFFFFFFFFu, np4[i+2], 8);
            float v = np2[0] + __shfl_xor_sync(0xFFFFFFFFu, np2[1], 4);
            v += __shfl_xor_sync(0xFFFFFFFFu, v, 1);
            v += __shfl_xor_sync(0xFFFFFFFFu, v, 2);
            if (isWriter) {
                const float h = v + bga;
                g_h1[(p*KK + k)*AA + aBase] = h;
                s2 += h; q2 += h*h;
            }
        }
        __syncwarp();
        cur ^= 1;
        p = pn;
    }
    if (isWriter) {
        atomicAdd(&red[aBase],     s2);
        atomicAdd(&red[8 + aBase], q2);
    }
    __syncthreads();
    // g_acc[134..141]=sum, g_acc[142..149]=sq -> contiguous with red[0..15]
    if (t < 16) atomicAdd(&g_acc[134 + t], (double)red[t]);
    // last block finalizes the 8-channel g2-BN into g_bn[134..149]
    if (last_block(2, t, &sLast)) {
        if (t < 8) {
            const double inv = 1.0 / (double)ITEMS;
            const double m = __ldcg(&g_acc[134 + t]) * inv;
            const double v = __ldcg(&g_acc[142 + t]) * inv - m*m;
            const float a = g2g[t] * rsqrtf((float)v + 1e-5f);
            g_bn[134 + t] = a;
            g_bn[142 + t] = be2[t] - (float)m * a;
        }
    }
}

// ---------------- kernel 5: h2/softmax (32-lane staging) + aggregation -----
__global__ void __launch_bounds__(256, 4) k_final(
                        const int* __restrict__ knn, const float* __restrict__ Wd2,
                        const float* __restrict__ bd2p, const float* __restrict__ Wg2,
                        const float* __restrict__ bg2, float* __restrict__ out) {
    __shared__ float sWg2[64], sa2[8], sb2[8], sbg2[8];
    __shared__ float sattn[8][2][16][8];
    __shared__ float st[8][2][16][4];
    __shared__ int   sidx[8][2][16];
    const int t = threadIdx.x;
    if (t < 64) sWg2[t] = Wg2[t];
    if (t < 8) { sa2[t] = g_bn[134+t]; sb2[t] = g_bn[142+t]; sbg2[t] = bg2[t]; }
    __syncthreads();
    const int lane = t & 31, w = t >> 5;
    const int nw   = (gridDim.x * blockDim.x) >> 5;
    const int warp = (blockIdx.x * blockDim.x + t) >> 5;
    const int c = lane * 2;
    const float ad0=g_bn[0], ad1=g_bn[1], ad2=g_bn[2];
    const float bd0=g_bn[3], bd1v=g_bn[4], bd2v=g_bn[5];
    const float2 wr0 = *(const float2*)(Wd2 + c);
    const float2 wr1 = *(const float2*)(Wd2 + 64 + c);
    const float2 wr2 = *(const float2*)(Wd2 + 128 + c);
    const float2 bb  = *(const float2*)(bd2p + c);
    const int a = c & 7;          // even; lane covers attn indices a, a+1
    const int kk   = lane & 15;   // staging: k index
    const int half = lane >> 4;   // staging: 0 -> x 0..3, 1 -> x 4..7
    const int xb   = half * 4;

    // ---- staging lambda (all 32 lanes) ----
    auto stage = [&](int pp, int buf) {
        const int j = knn[pp*KK + kk];
        if (half == 0) sidx[w][buf][kk] = j;
        const float* hp = g_h1 + (pp*KK + kk)*AA;
        float z[8];
        #pragma unroll
        for (int x = 0; x < 8; x++) z[x] = fmaxf(sa2[x]*hp[x] + sb2[x], 0.f);
        float h2[4];
        #pragma unroll
        for (int i = 0; i < 4; i++) {
            float acc = sbg2[xb + i];
            #pragma unroll
            for (int jj = 0; jj < 8; jj++) acc += z[jj]*sWg2[jj*8 + xb + i];
            h2[i] = acc;
        }
        float mx[4];
        #pragma unroll
        for (int i = 0; i < 4; i++) mx[i] = h2[i];
        #pragma unroll
        for (int off = 8; off; off >>= 1)
            #pragma unroll
            for (int i = 0; i < 4; i++)
                mx[i] = fmaxf(mx[i], __shfl_xor_sync(0xFFFFFFFFu, mx[i], off));
        float ex[4], sm[4];
        #pragma unroll
        for (int i = 0; i < 4; i++) { ex[i] = __expf(h2[i] - mx[i]); sm[i] = ex[i]; }
        #pragma unroll
        for (int off = 8; off; off >>= 1)
            #pragma unroll
            for (int i = 0; i < 4; i++)
                sm[i] += __shfl_xor_sync(0xFFFFFFFFu, sm[i], off);
        #pragma unroll
        for (int i = 0; i < 4; i++) sattn[w][buf][kk][xb + i] = __fdividef(ex[i], sm[i]);
        if (half == 0) {
            const float* dpp = g_d1 + (pp*KK + kk)*3;
            st[w][buf][kk][0] = fmaxf(ad0*dpp[0] + bd0,  0.f);
            st[w][buf][kk][1] = fmaxf(ad1*dpp[1] + bd1v, 0.f);
            st[w][buf][kk][2] = fmaxf(ad2*dpp[2] + bd2v, 0.f);
        }
    };

    int cur = 0;
    int p = warp;
    stage(p, 0);
    __syncwarp();
    while (p < PTS) {
        const int pn = p + nw;
        if (pn < PTS) stage(pn, cur ^ 1);
        const int b = p >> 14;
        float acc0 = 0.f, acc1 = 0.f;
        #pragma unroll
        for (int k = 0; k < KK; k++) {
            const int j = sidx[w][cur][k];
            const float2 vr = *(const float2*)(g_v + ((b<<14) + j)*CC + c);
            const float t0 = st[w][cur][k][0], t1 = st[w][cur][k][1], t2 = st[w][cur][k][2];
            const float2 at = *(const float2*)(&sattn[w][cur][k][a]);
            acc0 += (vr.x + t0*wr0.x + t1*wr1.x + t2*wr2.x + bb.x) * at.x;
            acc1 += (vr.y + t0*wr0.y + t1*wr1.y + t2*wr2.y + bb.y) * at.y;
        }
        *(float2*)(out + p*CC + c) = make_float2(acc0, acc1);
        __syncwarp();
        cur ^= 1;
        p = pn;
    }
}

// ---------------- launch ----------------------------------------------------
extern "C" void kernel_launch(void* const* d_in, const int* in_sizes, int n_in,
                              void* d_out, int out_size) {
    const float* xyz  = (const float*)d_in[0];
    const float* feat = (const float*)d_in[1];
    const int*   knn  = (const int*)  d_in[2];
    const float* Wq   = (const float*)d_in[3];  const float* bq  = (const float*)d_in[4];
    const float* Wk   = (const float*)d_in[5];  const float* bk  = (const float*)d_in[6];
    const float* Wv   = (const float*)d_in[7];  const float* bv  = (const float*)d_in[8];
    const float* Wd1  = (const float*)d_in[9];  const float* bd1 = (const float*)d_in[10];
    const float* gd   = (const float*)d_in[11]; const float* bed = (const float*)d_in[12];
    const float* Wd2  = (const float*)d_in[13]; const float* bd2 = (const float*)d_in[14];
    const float* g1   = (const float*)d_in[15]; const float* be1 = (const float*)d_in[16];
    const float* Wg1  = (const float*)d_in[17]; const float* bg1 = (const float*)d_in[18];
    const float* g2   = (const float*)d_in[19]; const float* be2 = (const float*)d_in[20];
    const float* Wg2  = (const float*)d_in[21]; const float* bg2 = (const float*)d_in[22];
    float* out = (float*)d_out;

    k_qkv   <<<512, 256>>>(feat, Wq, bq, Wk, bk, Wv, bv);
    k_d1    <<<EVEN_GRID, 256>>>(xyz, knn, Wd1, bd1, gd, bed);
    k_g1s   <<<EVEN_GRID, 256>>>(knn, Wd2, bd2, g1, be1);
    k_h1    <<<EVEN_GRID, 256>>>(knn, Wd2, bd2, Wg1, bg1, g2, be2);
    k_final <<<EVEN_GRID, 256>>>(knn, Wd2, bd2, Wg2, bg2, out);
}

// round 16
// speedup vs baseline: 1.3885x; 1.0004x over previous
#include <cuda_runtime.h>

#define BB 2
#define NN 16384
#define KK 16
#define CC 64
#define AA 8
#define PTS (BB*NN)          // 32768 points
#define ITEMS (PTS*KK)       // 524288 (b,n,k) items
#define EVEN_GRID 592        // 4 blocks * 148 SMs

// ---------------- scratch (device globals; no allocation allowed) ----------
__device__ float    g_q [PTS*CC];
__device__ float    g_k [PTS*CC];
__device__ float    g_v [PTS*CC];
__device__ float    g_d1[ITEMS*3];
__device__ float    g_h1[ITEMS*AA];
// acc layout: [0..2]=d_sum [3..5]=d_sq [6..69]=g1_sum [70..133]=g1_sq
//             [134..141]=g2_sum [142..149]=g2_sq
__device__ double   g_acc[150];
// bn layout: [0..2]=a_d [3..5]=b_d [6..69]=a1 [70..133]=b1 [134..141]=a2 [142..149]=b2
__device__ float    g_bn[150];
__device__ unsigned g_ctr[4];    // 0=d1, 1=g1s, 2=h1

// last-block detector: returns true in exactly one block, after all others
// have finished their g_acc contributions.
__device__ __forceinline__ bool last_block(int ctrId, int t, int* sFlag) {
    __syncthreads();
    if (t == 0) {
        __threadfence();
        *sFlag = (atomicAdd(&g_ctr[ctrId], 1u) == gridDim.x - 1) ? 1 : 0;
    }
    __syncthreads();
    return *sFlag != 0;
}

// ---------------- kernel 1: q/k/v linear (4x4 register-tiled GEMM) ---------
__global__ void __launch_bounds__(256) k_qkv(
                      const float* __restrict__ feat,
                      const float* __restrict__ Wq, const float* __restrict__ bq,
                      const float* __restrict__ Wk, const float* __restrict__ bk,
                      const float* __restrict__ Wv, const float* __restrict__ bv) {
    if (blockIdx.x == 0) {
        if (threadIdx.x < 150) g_acc[threadIdx.x] = 0.0;
        else if (threadIdx.x < 154) g_ctr[threadIdx.x - 150] = 0u;
    }
    __shared__ float sF[64][65];
    __shared__ float sW[64][64];
    const int t  = threadIdx.x;        // 256
    const int tx = t & 15;             // col group: cols 4tx..4tx+3
    const int ty = t >> 4;             // row base:  rows ty, ty+16, ty+32, ty+48
    const int rowBase = blockIdx.x * 64;
    for (int i = t; i < 4096; i += 256) sF[i>>6][i&63] = feat[rowBase*64 + i];
    __syncthreads();
    for (int m = 0; m < 3; m++) {
        const float* W    = (m==0) ? Wq : ((m==1) ? Wk : Wv);
        const float* bptr = (m==0) ? bq : ((m==1) ? bk : bv);
        float* outp       = (m==0) ? g_q : ((m==1) ? g_k : g_v);
        for (int i = t; i < 4096; i += 256) sW[i>>6][i&63] = W[i];
        __syncthreads();
        const float4 bias = *(const float4*)(bptr + 4*tx);
        float4 acc[4];
        #pragma unroll
        for (int r = 0; r < 4; r++) acc[r] = bias;
        #pragma unroll
        for (int i = 0; i < 64; i++) {
            const float4 wv = *(const float4*)&sW[i][4*tx];
            const float f0 = sF[ty     ][i];
            const float f1 = sF[ty + 16][i];
            const float f2 = sF[ty + 32][i];
            const float f3 = sF[ty + 48][i];
            acc[0].x += f0*wv.x; acc[0].y += f0*wv.y; acc[0].z += f0*wv.z; acc[0].w += f0*wv.w;
            acc[1].x += f1*wv.x; acc[1].y += f1*wv.y; acc[1].z += f1*wv.z; acc[1].w += f1*wv.w;
            acc[2].x += f2*wv.x; acc[2].y += f2*wv.y; acc[2].z += f2*wv.z; acc[2].w += f2*wv.w;
            acc[3].x += f3*wv.x; acc[3].y += f3*wv.y; acc[3].z += f3*wv.z; acc[3].w += f3*wv.w;
        }
        #pragma unroll
        for (int r = 0; r < 4; r++)
            *(float4*)&outp[(rowBase + ty + 16*r)*CC + 4*tx] = acc[r];
        __syncthreads();
    }
}

// ---------------- kernel 2: d1 = rel @ Wd1 + bd1, stats, inline d-BN fin ---
__global__ void __launch_bounds__(256) k_d1(
                     const float* __restrict__ xyz, const int* __restrict__ knn,
                     const float* __restrict__ Wd1, const float* __restrict__ bd1,
                     const float* __restrict__ gd, const float* __restrict__ bed) {
    __shared__ float red[6];
    __shared__ int sLast;
    if (threadIdx.x < 6) red[threadIdx.x] = 0.f;
    __syncthreads();
    float w[9], bb[3];
    #pragma unroll
    for (int i = 0; i < 9; i++) w[i] = Wd1[i];
    #pragma unroll
    for (int i = 0; i < 3; i++) bb[i] = bd1[i];
    float s[3] = {0,0,0}, qq[3] = {0,0,0};
    const int stride = gridDim.x * blockDim.x;
    for (int id = blockIdx.x*blockDim.x + threadIdx.x; id < ITEMS; id += stride) {
        const int p = id >> 4;
        const int b = p >> 14;
        const int n = p & (NN-1);
        const int j = knn[id];
        const float* xc = xyz + (b*NN + n)*3;
        const float* xn = xyz + (b*NN + j)*3;
        const float r0 = xc[0]-xn[0], r1 = xc[1]-xn[1], r2 = xc[2]-xn[2];
        #pragma unroll
        for (int c = 0; c < 3; c++) {
            const float d = r0*w[c] + r1*w[3+c] + r2*w[6+c] + bb[c];
            g_d1[id*3 + c] = d;
            s[c] += d; qq[c] += d*d;
        }
    }
    #pragma unroll
    for (int c = 0; c < 3; c++) {
        #pragma unroll
        for (int off = 16; off; off >>= 1) {
            s[c]  += __shfl_xor_sync(0xFFFFFFFFu, s[c],  off);
            qq[c] += __shfl_xor_sync(0xFFFFFFFFu, qq[c], off);
        }
    }
    if ((threadIdx.x & 31) == 0) {
        #pragma unroll
        for (int c = 0; c < 3; c++) {
            atomicAdd(&red[c],     s[c]);
            atomicAdd(&red[3 + c], qq[c]);
        }
    }
    __syncthreads();
    if (threadIdx.x < 6)
        atomicAdd(&g_acc[threadIdx.x], (double)red[threadIdx.x]);
    // last block finalizes d-BN into g_bn[0..5]
    if (last_block(0, threadIdx.x, &sLast)) {
        const int c = threadIdx.x;
        if (c < 3) {
            const double inv = 1.0 / (double)ITEMS;
            const double m = __ldcg(&g_acc[c])     * inv;
            const double v = __ldcg(&g_acc[3 + c]) * inv - m*m;
            const float a = gd[c] * rsqrtf((float)v + 1e-5f);
            g_bn[c]     = a;
            g_bn[3 + c] = bed[c] - (float)m * a;
        }
    }
}

// ---------------- kernel 3: attn_in stats + inline g1-BN finalize ----------
__global__ void __launch_bounds__(256, 4) k_g1s(
                      const int* __restrict__ knn, const float* __restrict__ Wd2,
                      const float* __restrict__ bd2p,
                      const float* __restrict__ g1g, const float* __restrict__ be1) {
    __shared__ float st[8][2][16][4];
    __shared__ int   sj[8][2][16];
    __shared__ float red[128];   // [0..63]=sum per channel, [64..127]=sq
    __shared__ int   sLast;
    const int t = threadIdx.x;
    if (t < 128) red[t] = 0.f;
    __syncthreads();
    const int lane = t & 31, w = t >> 5;
    const int warp = (blockIdx.x*blockDim.x + t) >> 5;
    const int nw   = (gridDim.x*blockDim.x) >> 5;
    const int c = lane * 2;
    const float ad0=g_bn[0], ad1=g_bn[1], ad2=g_bn[2];
    const float bd0=g_bn[3], bd1v=g_bn[4], bd2v=g_bn[5];
    const float2 wr0 = *(const float2*)(Wd2 + c);
    const float2 wr1 = *(const float2*)(Wd2 + 64 + c);
    const float2 wr2 = *(const float2*)(Wd2 + 128 + c);
    const float2 bb  = *(const float2*)(bd2p + c);
    float s0=0, s1=0, q0=0, q1=0;
    int cur = 0;
    int p = warp;                       // warp < 4736 < PTS always
    if (lane < 16) {
        sj[w][0][lane] = knn[p*KK + lane];
        const float* dp = g_d1 + (p*KK + lane)*3;
        st[w][0][lane][0] = fmaxf(ad0*dp[0] + bd0,  0.f);
        st[w][0][lane][1] = fmaxf(ad1*dp[1] + bd1v, 0.f);
        st[w][0][lane][2] = fmaxf(ad2*dp[2] + bd2v, 0.f);
    }
    __syncwarp();
    while (p < PTS) {
        const int pn = p + nw;
        if (pn < PTS && lane < 16) {
            const int nb = cur ^ 1;
            sj[w][nb][lane] = knn[pn*KK + lane];
            const float* dp = g_d1 + (pn*KK + lane)*3;
            st[w][nb][lane][0] = fmaxf(ad0*dp[0] + bd0,  0.f);
            st[w][nb][lane][1] = fmaxf(ad1*dp[1] + bd1v, 0.f);
            st[w][nb][lane][2] = fmaxf(ad2*dp[2] + bd2v, 0.f);
        }
        const int b = p >> 14;
        const float2 qv = *(const float2*)(g_q + p*CC + c);
        #pragma unroll
        for (int k = 0; k < KK; k++) {
            const int j = sj[w][cur][k];
            const float t0 = st[w][cur][k][0], t1 = st[w][cur][k][1], t2 = st[w][cur][k][2];
            const float2 kr = *(const float2*)(g_k + ((b<<14) + j)*CC + c);
            const float x0 = qv.x - kr.x + t0*wr0.x + t1*wr1.x + t2*wr2.x + bb.x;
            const float x1 = qv.y - kr.y + t0*wr0.y + t1*wr1.y + t2*wr2.y + bb.y;
            s0 += x0; q0 += x0*x0; s1 += x1; q1 += x1*x1;
        }
        __syncwarp();
        cur ^= 1;
        p = pn;
    }
    atomicAdd(&red[c],        s0);
    atomicAdd(&red[c + 1],    s1);
    atomicAdd(&red[64 + c],   q0);
    atomicAdd(&red[64 + c+1], q1);
    __syncthreads();
    // g_acc[6..69]=sum, g_acc[70..133]=sq  -> contiguous with red[0..127]
    if (t < 128) atomicAdd(&g_acc[6 + t], (double)red[t]);
    // last block finalizes the 64-channel g1-BN into g_bn[6..133]
    if (last_block(1, t, &sLast)) {
        if (t < 64) {
            const double inv = 1.0 / (double)ITEMS;
            const double m = __ldcg(&g_acc[6 + t])  * inv;
            const double v = __ldcg(&g_acc[70 + t]) * inv - m*m;
            const float a = g1g[t] * rsqrtf((float)v + 1e-5f);
            g_bn[6 + t]  = a;
            g_bn[70 + t] = be1[t] - (float)m * a;
        }
    }
}

// ---------------- kernel 4: h1 pass + inline g2-BN finalize ----------------
// g1-BN affine folded into constants: y = max(fma(-a1,kr,qp) + sum t_d*wr'_d, 0)
// Weights pre-permuted (slot i holds output aBase^i) -> select-free butterfly.
__global__ void __launch_bounds__(256, 4) k_h1(
                     const int* __restrict__ knn, const float* __restrict__ Wd2,
                     const float* __restrict__ bd2p, const float* __restrict__ Wg1,
                     const float* __restrict__ bg1,
                     const float* __restrict__ g2g, const float* __restrict__ be2) {
    __shared__ float st[8][2][16][4];
    __shared__ int   sj[8][2][16];
    __shared__ float red[16];    // [0..7]=sum, [8..15]=sq
    __shared__ int   sLast;
    const int t = threadIdx.x;
    if (t < 16) red[t] = 0.f;
    __syncthreads();
    const int lane = t & 31, w = t >> 5;
    const int warp = (blockIdx.x*blockDim.x + t) >> 5;
    const int nw   = (gridDim.x*blockDim.x) >> 5;
    const int c = lane * 2;
    const float ad0=g_bn[0], ad1=g_bn[1], ad2=g_bn[2];
    const float bd0=g_bn[3], bd1v=g_bn[4], bd2v=g_bn[5];
    const float2 a1  = *(const float2*)(g_bn + 6 + c);
    const float2 b1  = *(const float2*)(g_bn + 70 + c);
    // fold a1 into pos-enc weights and bias
    const float2 wr0r = *(const float2*)(Wd2 + c);
    const float2 wr1r = *(const float2*)(Wd2 + 64 + c);
    const float2 wr2r = *(const float2*)(Wd2 + 128 + c);
    const float2 bbr  = *(const float2*)(bd2p + c);
    const float2 wr0 = make_float2(a1.x*wr0r.x, a1.y*wr0r.y);
    const float2 wr1 = make_float2(a1.x*wr1r.x, a1.y*wr1r.y);
    const float2 wr2 = make_float2(a1.x*wr2r.x, a1.y*wr2r.y);
    const float2 bbf = make_float2(a1.x*bbr.x + b1.x, a1.y*bbr.y + b1.y);
    const float2 na1 = make_float2(-a1.x, -a1.y);
    const int aBase = (lane >> 2) & 7;           // output this lane ends up with
    // permuted weights: slot i <-> output (aBase ^ i)
    float wgA[8], wgB[8];
    #pragma unroll
    for (int i = 0; i < 8; i++) {
        wgA[i] = Wg1[c*8     + (aBase ^ i)];
        wgB[i] = Wg1[(c+1)*8 + (aBase ^ i)];
    }
    const bool isWriter = ((lane & 3) == 0);
    const float bga = bg1[aBase];
    float s2 = 0.f, q2 = 0.f;
    int cur = 0;
    int p = warp;
    if (lane < 16) {
        sj[w][0][lane] = knn[p*KK + lane];
        const float* dp = g_d1 + (p*KK + lane)*3;
        st[w][0][lane][0] = fmaxf(ad0*dp[0] + bd0,  0.f);
        st[w][0][lane][1] = fmaxf(ad1*dp[1] + bd1v, 0.f);
        st[w][0][lane][2] = fmaxf(ad2*dp[2] + bd2v, 0.f);
    }
    __syncwarp();
    while (p < PTS) {
        const int pn = p + nw;
        if (pn < PTS && lane < 16) {
            const int nb = cur ^ 1;
            sj[w][nb][lane] = knn[pn*KK + lane];
            const float* dp = g_d1 + (pn*KK + lane)*3;
            st[w][nb][lane][0] = fmaxf(ad0*dp[0] + bd0,  0.f);
            st[w][nb][lane][1] = fmaxf(ad1*dp[1] + bd1v, 0.f);
            st[w][nb][lane][2] = fmaxf(ad2*dp[2] + bd2v, 0.f);
        }
        const int b = p >> 14;
        const float2 qv = *(const float2*)(g_q + p*CC + c);
        // per-point folded q: qp = a1*q + bbf
        const float2 qp = make_float2(a1.x*qv.x + bbf.x, a1.y*qv.y + bbf.y);
        #pragma unroll 8
        for (int k = 0; k < KK; k++) {
            const int j = sj[w][cur][k];
            const float t0 = st[w][cur][k][0], t1 = st[w][cur][k][1], t2 = st[w][cur][k][2];
            const float2 kr = *(const float2*)(g_k + ((b<<14) + j)*CC + c);
            float y0 = fmaf(na1.x, kr.x, qp.x);
            float y1 = fmaf(na1.y, kr.y, qp.y);
            y0 = fmaf(t0, wr0.x, y0); y1 = fmaf(t0, wr0.y, y1);
            y0 = fmaf(t1, wr1.x, y0); y1 = fmaf(t1, wr1.y, y1);
            y0 = fmaf(t2, wr2.x, y0); y1 = fmaf(t2, wr2.y, y1);
            y0 = fmaxf(y0, 0.f);
            y1 = fmaxf(y1, 0.f);
            float part[8];
            #pragma unroll
            for (int i = 0; i < 8; i++) part[i] = y0*wgA[i] + y1*wgB[i];
            // select-free value-splitting butterfly (slot i == output aBase^i)
            float np4[4];
            #pragma unroll
            for (int i = 0; i < 4; i++)
                np4[i] = part[i] + __shfl_xor_sync(0xFFFFFFFFu, part[i+4], 16);
            float np2[2];
            #pragma unroll
            for (int i = 0; i < 2; i++)
                np2[i] = np4[i] + __shfl_xor_sync(0xFFFFFFFFu, np4[i+2], 8);
            float v = np2[0] + __shfl_xor_sync(0xFFFFFFFFu, np2[1], 4);
            v += __shfl_xor_sync(0xFFFFFFFFu, v, 1);
            v += __shfl_xor_sync(0xFFFFFFFFu, v, 2);
            if (isWriter) {
                const float h = v + bga;
                g_h1[(p*KK + k)*AA + aBase] = h;
                s2 += h; q2 += h*h;
            }
        }
        __syncwarp();
        cur ^= 1;
        p = pn;
    }
    if (isWriter) {
        atomicAdd(&red[aBase],     s2);
        atomicAdd(&red[8 + aBase], q2);
    }
    __syncthreads();
    // g_acc[134..141]=sum, g_acc[142..149]=sq -> contiguous with red[0..15]
    if (t < 16) atomicAdd(&g_acc[134 + t], (double)red[t]);
    // last block finalizes the 8-channel g2-BN into g_bn[134..149]
    if (last_block(2, t, &sLast)) {
        if (t < 8) {
            const double inv = 1.0 / (double)ITEMS;
            const double m = __ldcg(&g_acc[134 + t]) * inv;
            const double v = __ldcg(&g_acc[142 + t]) * inv - m*m;
            const float a = g2g[t] * rsqrtf((float)v + 1e-5f);
            g_bn[134 + t] = a;
            g_bn[142 + t] = be2[t] - (float)m * a;
        }
    }
}

// ---------------- kernel 5: h2/softmax (32-lane staging) + aggregation -----
__global__ void __launch_bounds__(256, 4) k_final(
                        const int* __restrict__ knn, const float* __restrict__ Wd2,
                        const float* __restrict__ bd2p, const float* __restrict__ Wg2,
                        const float* __restrict__ bg2, float* __restrict__ out) {
    __shared__ float sWg2[64], sa2[8], sb2[8], sbg2[8];
    __shared__ float sattn[8][2][16][8];
    __shared__ float st[8][2][16][4];
    __shared__ int   sidx[8][2][16];
    const int t = threadIdx.x;
    if (t < 64) sWg2[t] = Wg2[t];
    if (t < 8) { sa2[t] = g_bn[134+t]; sb2[t] = g_bn[142+t]; sbg2[t] = bg2[t]; }
    __syncthreads();
    const int lane = t & 31, w = t >> 5;
    const int nw   = (gridDim.x * blockDim.x) >> 5;
    const int warp = (blockIdx.x * blockDim.x + t) >> 5;
    const int c = lane * 2;
    const float ad0=g_bn[0], ad1=g_bn[1], ad2=g_bn[2];
    const float bd0=g_bn[3], bd1v=g_bn[4], bd2v=g_bn[5];
    const float2 wr0 = *(const float2*)(Wd2 + c);
    const float2 wr1 = *(const float2*)(Wd2 + 64 + c);
    const float2 wr2 = *(const float2*)(Wd2 + 128 + c);
    const float2 bb  = *(const float2*)(bd2p + c);
    const int a = c & 7;          // even; lane covers attn indices a, a+1
    const int kk   = lane & 15;   // staging: k index
    const int half = lane >> 4;   // staging: 0 -> x 0..3, 1 -> x 4..7
    const int xb   = half * 4;

    // ---- staging lambda (all 32 lanes) ----
    auto stage = [&](int pp, int buf) {
        const int j = knn[pp*KK + kk];
        if (half == 0) sidx[w][buf][kk] = j;
        const float* hp = g_h1 + (pp*KK + kk)*AA;
        float z[8];
        #pragma unroll
        for (int x = 0; x < 8; x++) z[x] = fmaxf(sa2[x]*hp[x] + sb2[x], 0.f);
        float h2[4];
        #pragma unroll
        for (int i = 0; i < 4; i++) {
            float acc = sbg2[xb + i];
            #pragma unroll
            for (int jj = 0; jj < 8; jj++) acc += z[jj]*sWg2[jj*8 + xb + i];
            h2[i] = acc;
        }
        float mx[4];
        #pragma unroll
        for (int i = 0; i < 4; i++) mx[i] = h2[i];
        #pragma unroll
        for (int off = 8; off; off >>= 1)
            #pragma unroll
            for (int i = 0; i < 4; i++)
                mx[i] = fmaxf(mx[i], __shfl_xor_sync(0xFFFFFFFFu, mx[i], off));
        float ex[4], sm[4];
        #pragma unroll
        for (int i = 0; i < 4; i++) { ex[i] = __expf(h2[i] - mx[i]); sm[i] = ex[i]; }
        #pragma unroll
        for (int off = 8; off; off >>= 1)
            #pragma unroll
            for (int i = 0; i < 4; i++)
                sm[i] += __shfl_xor_sync(0xFFFFFFFFu, sm[i], off);
        #pragma unroll
        for (int i = 0; i < 4; i++) sattn[w][buf][kk][xb + i] = __fdividef(ex[i], sm[i]);
        if (half == 0) {
            const float* dpp = g_d1 + (pp*KK + kk)*3;
            st[w][buf][kk][0] = fmaxf(ad0*dpp[0] + bd0,  0.f);
            st[w][buf][kk][1] = fmaxf(ad1*dpp[1] + bd1v, 0.f);
            st[w][buf][kk][2] = fmaxf(ad2*dpp[2] + bd2v, 0.f);
        }
    };

    int cur = 0;
    int p = warp;
    stage(p, 0);
    __syncwarp();
    while (p < PTS) {
        const int pn = p + nw;
        if (pn < PTS) stage(pn, cur ^ 1);
        const int b = p >> 14;
        float acc0 = 0.f, acc1 = 0.f;
        #pragma unroll
        for (int k = 0; k < KK; k++) {
            const int j = sidx[w][cur][k];
            const float2 vr = *(const float2*)(g_v + ((b<<14) + j)*CC + c);
            const float t0 = st[w][cur][k][0], t1 = st[w][cur][k][1], t2 = st[w][cur][k][2];
            const float2 at = *(const float2*)(&sattn[w][cur][k][a]);
            acc0 += (vr.x + t0*wr0.x + t1*wr1.x + t2*wr2.x + bb.x) * at.x;
            acc1 += (vr.y + t0*wr0.y + t1*wr1.y + t2*wr2.y + bb.y) * at.y;
        }
        *(float2*)(out + p*CC + c) = make_float2(acc0, acc1);
        __syncwarp();
        cur ^= 1;
        p = pn;
    }
}

// ---------------- launch ----------------------------------------------------
extern "C" void kernel_launch(void* const* d_in, const int* in_sizes, int n_in,
                              void* d_out, int out_size) {
    const float* xyz  = (const float*)d_in[0];
    const float* feat = (const float*)d_in[1];
    const int*   knn  = (const int*)  d_in[2];
    const float* Wq   = (const float*)d_in[3];  const float* bq  = (const float*)d_in[4];
    const float* Wk   = (const float*)d_in[5];  const float* bk  = (const float*)d_in[6];
    const float* Wv   = (const float*)d_in[7];  const float* bv  = (const float*)d_in[8];
    const float* Wd1  = (const float*)d_in[9];  const float* bd1 = (const float*)d_in[10];
    const float* gd   = (const float*)d_in[11]; const float* bed = (const float*)d_in[12];
    const float* Wd2  = (const float*)d_in[13]; const float* bd2 = (const float*)d_in[14];
    const float* g1   = (const float*)d_in[15]; const float* be1 = (const float*)d_in[16];
    const float* Wg1  = (const float*)d_in[17]; const float* bg1 = (const float*)d_in[18];
    const float* g2   = (const float*)d_in[19]; const float* be2 = (const float*)d_in[20];
    const float* Wg2  = (const float*)d_in[21]; const float* bg2 = (const float*)d_in[22];
    float* out = (float*)d_out;

    k_qkv   <<<512, 256>>>(feat, Wq, bq, Wk, bk, Wv, bv);
    k_d1    <<<EVEN_GRID, 256>>>(xyz, knn, Wd1, bd1, gd, bed);
    k_g1s   <<<EVEN_GRID, 256>>>(knn, Wd2, bd2, g1, be1);
    k_h1    <<<EVEN_GRID, 256>>>(knn, Wd2, bd2, Wg1, bg1, g2, be2);
    k_final <<<EVEN_GRID, 256>>>(knn, Wd2, bd2, Wg2, bg2, out);
}